// round 1
// baseline (speedup 1.0000x reference)
#include <cuda_runtime.h>
#include <math.h>

// ---------------------------------------------------------------------------
// ComplexRecurrentModel: B=4, S=128, D=512, M=4, K=32, STEPS=16
// Round 0: correct fp32 implementation. Heavy work = complex GEMMs (tiled
// 64x64x16 SGEMM, fp32). ~230 kernel launches, all graph-capturable.
// ---------------------------------------------------------------------------

#define Bc 4
#define Sc 128
#define Dc 512
#define Mc 4
#define Kc 32
#define NSTEPS 16
#define EPSF 1e-6f
#define SCALEF 0.044194173824159216f   // 512^-0.5

constexpr int NBSD  = Bc * Sc * Dc;        // 262144
constexpr int NMBSD = Mc * Bc * Sc * Dc;   // 1048576
constexpr int NBS   = Bc * Sc;             // 512
constexpr int NMBS  = Mc * Bc * Sc;        // 2048

// ---- scratch arena offsets (floats), all 16-float aligned ----
constexpr int O_CR   = 0;
constexpr int O_CI   = O_CR + NBSD;
constexpr int O_ZR   = O_CI + NBSD;
constexpr int O_ZI   = O_ZR + NMBSD;
constexpr int O_QR   = O_ZI + NMBSD;
constexpr int O_QI   = O_QR + NMBSD;
constexpr int O_KR   = O_QI + NMBSD;
constexpr int O_KI   = O_KR + NMBSD;
constexpr int O_VR   = O_KI + NMBSD;
constexpr int O_VI   = O_VR + NMBSD;
constexpr int O_AT   = O_VI + NMBSD;               // M*B*S*S
constexpr int O_PR   = O_AT + Mc * Bc * Sc * Sc;
constexpr int O_PI   = O_PR + NMBSD;
constexpr int O_SR   = O_PI + NMBSD;
constexpr int O_SI   = O_SR + NBSD;
constexpr int O_MEM  = O_SI + NBSD;                // B*K*2D
constexpr int O_ACC  = O_MEM + Bc * Kc * 2 * Dc;   // B*S*2D
constexpr int O_PTR  = O_ACC + Bc * Sc * 2 * Dc;   // B*K
constexpr int O_SCORE= O_PTR + Bc * Kc;
constexpr int O_CONF = O_SCORE + NMBS;
constexpr int O_HALT = O_CONF + NMBS;
constexpr int O_FLAT = O_HALT + NMBS;              // B*2D
constexpr int O_READ = O_FLAT + Bc * 2 * Dc;       // B*2D
constexpr int O_WMASK= O_READ + Bc * 2 * Dc;       // B*K
constexpr int O_GATE = O_WMASK + Bc * Kc;          // M*D (sigmoid(gate_mask))
constexpr int O_REM  = O_GATE + Mc * Dc;           // B (padded 16)
constexpr int O_STSC = O_REM + 16;
constexpr int O_STCF = O_STSC + 16;
constexpr int O_COEF = O_STCF + 16;
constexpr int TOTALF = O_COEF + 16;

__device__ __align__(256) float g_scratch[TOTALF];

// ---------------------------------------------------------------------------
// helpers
// ---------------------------------------------------------------------------
__device__ __forceinline__ float sigm(float x) { return 1.f / (1.f + expf(-x)); }

__device__ __forceinline__ float blockSum128(float v) {
    __shared__ float sh[4];
    int lane = threadIdx.x & 31, w = threadIdx.x >> 5;
#pragma unroll
    for (int o = 16; o; o >>= 1) v += __shfl_xor_sync(0xffffffffu, v, o);
    if (lane == 0) sh[w] = v;
    __syncthreads();
    float r = sh[0] + sh[1] + sh[2] + sh[3];
    __syncthreads();
    return r;
}

__device__ __forceinline__ float blockMax128(float v) {
    __shared__ float sh[4];
    int lane = threadIdx.x & 31, w = threadIdx.x >> 5;
#pragma unroll
    for (int o = 16; o; o >>= 1) v = fmaxf(v, __shfl_xor_sync(0xffffffffu, v, o));
    if (lane == 0) sh[w] = v;
    __syncthreads();
    float r = fmaxf(fmaxf(sh[0], sh[1]), fmaxf(sh[2], sh[3]));
    __syncthreads();
    return r;
}

// ---------------------------------------------------------------------------
// init: sr=x_real, si=x_imag, mem=0, ptr=onehot, acc=0, rem=1, gate=sigmoid(gm)
// ---------------------------------------------------------------------------
__global__ void k_init(const float* __restrict__ xr, const float* __restrict__ xi,
                       const float* __restrict__ gate_mask) {
    int i = blockIdx.x * 256 + threadIdx.x;   // grid covers 524288
    float* S = g_scratch;
    if (i < NBSD) { S[O_SR + i] = xr[i]; S[O_SI + i] = xi[i]; }
    if (i < Bc * Sc * 2 * Dc) S[O_ACC + i] = 0.f;
    if (i < Bc * Kc * 2 * Dc) S[O_MEM + i] = 0.f;
    if (i < Bc * Kc) S[O_PTR + i] = (i % Kc == 0) ? 1.f : 0.f;
    if (i < Mc * Dc) S[O_GATE + i] = sigm(gate_mask[i]);
    if (i < Bc) S[O_REM + i] = 1.f;
}

// cr = 0.5*(x + s)
__global__ void k_pre(const float* __restrict__ xr, const float* __restrict__ xi) {
    int i = blockIdx.x * 256 + threadIdx.x;   // exactly NBSD
    float* S = g_scratch;
    S[O_CR + i] = 0.5f * (xr[i] + S[O_SR + i]);
    S[O_CI + i] = 0.5f * (xi[i] + S[O_SI + i]);
}

// ---------------------------------------------------------------------------
// Complex GEMM (NT): C[row,col] = sum_k A[row,k] * W[col,k] (complex or conj)
// CONJ=false:  cr = ar*br - ai*bi ; ci = ai*br + ar*bi
// CONJ=true :  cr = ar*br + ai*bi (real part of A * conj(B)^T); ci unused
// ---------------------------------------------------------------------------
template <bool CONJ, bool WI>
__global__ void __launch_bounds__(256) gemm_nt(
    const float* __restrict__ Ar, const float* __restrict__ Ai, int aMod,
    const float* __restrict__ Br, const float* __restrict__ Bi, int bMod,
    float* __restrict__ Cr, float* __restrict__ Ci, int cMod,
    int kdim, int ncols, float scale) {
    __shared__ float sAr[16][68], sAi[16][68], sBr[16][68], sBi[16][68];
    const int z = blockIdx.z;
    const float* ar = Ar + (size_t)z * aMod;
    const float* ai = Ai + (size_t)z * aMod;
    const float* br = Br + (size_t)z * bMod;
    const float* bi = Bi + (size_t)z * bMod;
    float* cr = Cr + (size_t)z * cMod;
    float* ci = WI ? (Ci + (size_t)z * cMod) : Cr;
    const int row0 = blockIdx.y * 64, col0 = blockIdx.x * 64;
    const int tid = threadIdx.x;
    const int lr = tid >> 2, lk = (tid & 3) * 4;
    const int ty = tid >> 4, tx = tid & 15;
    float accr[4][4], acci[4][4];
#pragma unroll
    for (int i = 0; i < 4; i++)
#pragma unroll
        for (int j = 0; j < 4; j++) { accr[i][j] = 0.f; acci[i][j] = 0.f; }
    const float* aP  = ar + (size_t)(row0 + lr) * kdim + lk;
    const float* aPi = ai + (size_t)(row0 + lr) * kdim + lk;
    const float* bP  = br + (size_t)(col0 + lr) * kdim + lk;
    const float* bPi = bi + (size_t)(col0 + lr) * kdim + lk;
    for (int k0 = 0; k0 < kdim; k0 += 16) {
        float4 a4  = *(const float4*)(aP + k0);
        float4 a4i = *(const float4*)(aPi + k0);
        float4 b4  = *(const float4*)(bP + k0);
        float4 b4i = *(const float4*)(bPi + k0);
        sAr[lk + 0][lr] = a4.x;  sAr[lk + 1][lr] = a4.y;  sAr[lk + 2][lr] = a4.z;  sAr[lk + 3][lr] = a4.w;
        sAi[lk + 0][lr] = a4i.x; sAi[lk + 1][lr] = a4i.y; sAi[lk + 2][lr] = a4i.z; sAi[lk + 3][lr] = a4i.w;
        sBr[lk + 0][lr] = b4.x;  sBr[lk + 1][lr] = b4.y;  sBr[lk + 2][lr] = b4.z;  sBr[lk + 3][lr] = b4.w;
        sBi[lk + 0][lr] = b4i.x; sBi[lk + 1][lr] = b4i.y; sBi[lk + 2][lr] = b4i.z; sBi[lk + 3][lr] = b4i.w;
        __syncthreads();
#pragma unroll
        for (int kk = 0; kk < 16; kk++) {
            float4 xr4 = *(const float4*)&sAr[kk][ty * 4];
            float4 xi4 = *(const float4*)&sAi[kk][ty * 4];
            float4 yr4 = *(const float4*)&sBr[kk][tx * 4];
            float4 yi4 = *(const float4*)&sBi[kk][tx * 4];
            float axr[4] = {xr4.x, xr4.y, xr4.z, xr4.w};
            float axi[4] = {xi4.x, xi4.y, xi4.z, xi4.w};
            float byr[4] = {yr4.x, yr4.y, yr4.z, yr4.w};
            float byi[4] = {yi4.x, yi4.y, yi4.z, yi4.w};
#pragma unroll
            for (int i = 0; i < 4; i++)
#pragma unroll
                for (int j = 0; j < 4; j++) {
                    accr[i][j] = fmaf(axr[i], byr[j], accr[i][j]);
                    accr[i][j] = fmaf(axi[i], CONJ ? byi[j] : -byi[j], accr[i][j]);
                    if (WI) {
                        acci[i][j] = fmaf(axi[i], byr[j], acci[i][j]);
                        acci[i][j] = fmaf(axr[i], byi[j], acci[i][j]);
                    }
                }
        }
        __syncthreads();
    }
#pragma unroll
    for (int i = 0; i < 4; i++)
#pragma unroll
        for (int j = 0; j < 4; j++) {
            size_t o = (size_t)(row0 + ty * 4 + i) * ncols + col0 + tx * 4 + j;
            cr[o] = accr[i][j] * scale;
            if (WI) ci[o] = acci[i][j] * scale;
        }
}

// ---------------------------------------------------------------------------
// AV GEMM (NN): O[s,d] = sum_t Attn[z][s,t] * V[z*S+t, d]  (real A, complex V)
// grid (Dc/64, Sc/64, M*B)
// ---------------------------------------------------------------------------
__global__ void __launch_bounds__(256) gemm_av(
    const float* __restrict__ L, const float* __restrict__ Vr,
    const float* __restrict__ Vi, float* __restrict__ Or, float* __restrict__ Oi) {
    __shared__ float sA[16][68];
    __shared__ float sVr[16][64], sVi[16][64];
    const int z = blockIdx.z;
    const float* a  = L  + (size_t)z * Sc * Sc;
    const float* vr = Vr + (size_t)z * Sc * Dc;
    const float* vi = Vi + (size_t)z * Sc * Dc;
    const int col0 = blockIdx.x * 64, row0 = blockIdx.y * 64;
    const int tid = threadIdx.x;
    const int lr = tid >> 2, lk = (tid & 3) * 4;
    const int tr = tid >> 4, dc = (tid & 15) * 4;
    const int ty = tid >> 4, tx = tid & 15;
    float accr[4][4], acci[4][4];
#pragma unroll
    for (int i = 0; i < 4; i++)
#pragma unroll
        for (int j = 0; j < 4; j++) { accr[i][j] = 0.f; acci[i][j] = 0.f; }
    for (int k0 = 0; k0 < Sc; k0 += 16) {
        float4 a4 = *(const float4*)(a + (size_t)(row0 + lr) * Sc + k0 + lk);
        sA[lk + 0][lr] = a4.x; sA[lk + 1][lr] = a4.y; sA[lk + 2][lr] = a4.z; sA[lk + 3][lr] = a4.w;
        *(float4*)&sVr[tr][dc] = *(const float4*)(vr + (size_t)(k0 + tr) * Dc + col0 + dc);
        *(float4*)&sVi[tr][dc] = *(const float4*)(vi + (size_t)(k0 + tr) * Dc + col0 + dc);
        __syncthreads();
#pragma unroll
        for (int kk = 0; kk < 16; kk++) {
            float4 av4 = *(const float4*)&sA[kk][ty * 4];
            float4 r4  = *(const float4*)&sVr[kk][tx * 4];
            float4 i4  = *(const float4*)&sVi[kk][tx * 4];
            float av[4] = {av4.x, av4.y, av4.z, av4.w};
            float rr[4] = {r4.x, r4.y, r4.z, r4.w};
            float ii[4] = {i4.x, i4.y, i4.z, i4.w};
#pragma unroll
            for (int i = 0; i < 4; i++)
#pragma unroll
                for (int j = 0; j < 4; j++) {
                    accr[i][j] = fmaf(av[i], rr[j], accr[i][j]);
                    acci[i][j] = fmaf(av[i], ii[j], acci[i][j]);
                }
        }
        __syncthreads();
    }
#pragma unroll
    for (int i = 0; i < 4; i++)
#pragma unroll
        for (int j = 0; j < 4; j++) {
            size_t o = ((size_t)z * Sc + row0 + ty * 4 + i) * Dc + col0 + tx * 4 + j;
            Or[o] = accr[i][j];
            Oi[o] = acci[i][j];
        }
}

// ---------------------------------------------------------------------------
// magnitude layer-norm + phase restore + modReLU. one block per (m,bs) row.
// ---------------------------------------------------------------------------
__global__ void k_norm(const float* __restrict__ ln_scale,
                       const float* __restrict__ ln_shift,
                       const float* __restrict__ mod_bias) {
    const int row = blockIdx.x;            // [M][B*S]
    const int m = row / NBS;
    float* pr = g_scratch + O_ZR + (size_t)row * Dc;
    float* pi = g_scratch + O_ZI + (size_t)row * Dc;
    const int t = threadIdx.x;             // 128 threads, 4 elems each
    float4 r4 = *(const float4*)(pr + t * 4);
    float4 i4 = *(const float4*)(pi + t * 4);
    float vr[4] = {r4.x, r4.y, r4.z, r4.w};
    float vi[4] = {i4.x, i4.y, i4.z, i4.w};
    float mg[4];
    float s = 0.f, ss = 0.f;
#pragma unroll
    for (int q = 0; q < 4; q++) {
        mg[q] = sqrtf(vr[q] * vr[q] + vi[q] * vi[q]) + EPSF;
        s += mg[q]; ss += mg[q] * mg[q];
    }
    float sum = blockSum128(s);
    float sumsq = blockSum128(ss);
    float mean = sum * (1.f / Dc);
    float var = (sumsq - (float)Dc * mean * mean) * (1.f / (Dc - 1));
    float rstd = rsqrtf(var + EPSF);
#pragma unroll
    for (int q = 0; q < 4; q++) {
        int d = t * 4 + q;
        float nm = (mg[q] - mean) * rstd * ln_scale[m * Dc + d] + ln_shift[m * Dc + d];
        float hyp = sqrtf(vr[q] * vr[q] + vi[q] * vi[q]);
        float c, sn;
        if (hyp > 0.f) { float ih = 1.f / hyp; c = vr[q] * ih; sn = vi[q] * ih; }
        else { c = 1.f; sn = 0.f; }
        float zr2 = nm * c, zi2 = nm * sn;
        float nrm = fabsf(nm) + EPSF;
        float sc = fmaxf(nrm + mod_bias[m * Dc + d], 0.f) / nrm;
        vr[q] = zr2 * sc; vi[q] = zi2 * sc;
    }
    *(float4*)(pr + t * 4) = make_float4(vr[0], vr[1], vr[2], vr[3]);
    *(float4*)(pi + t * 4) = make_float4(vi[0], vi[1], vi[2], vi[3]);
}

// softmax over last dim of attn logits; one block (128 thr) per row
__global__ void k_softmax() {
    float* p = g_scratch + O_AT + (size_t)blockIdx.x * Sc;
    float v = p[threadIdx.x];
    float mx = blockMax128(v);
    float e = expf(v - mx);
    float su = blockSum128(e);
    p[threadIdx.x] = e / su;
}

// gate (precomputed sigmoid) + score/conf/halt dots. block per (m,bs) row.
__global__ void k_gatescore(const float* __restrict__ score_w, const float* __restrict__ score_b,
                            const float* __restrict__ conf_w,  const float* __restrict__ conf_b,
                            const float* __restrict__ halt_w,  const float* __restrict__ halt_b) {
    const int row = blockIdx.x;
    const int m = row / NBS;
    float* ar = g_scratch + O_PR + (size_t)row * Dc;
    float* ai = g_scratch + O_PI + (size_t)row * Dc;
    const float* gate = g_scratch + O_GATE + m * Dc;
    const int t = threadIdx.x;
    float4 r4 = *(const float4*)(ar + t * 4);
    float4 i4 = *(const float4*)(ai + t * 4);
    float rr[4] = {r4.x, r4.y, r4.z, r4.w};
    float ii[4] = {i4.x, i4.y, i4.z, i4.w};
    float sA = 0.f, cA = 0.f, hA = 0.f;
#pragma unroll
    for (int q = 0; q < 4; q++) {
        int d = t * 4 + q;
        float g = gate[d];
        rr[q] *= g; ii[q] *= g;
        sA += rr[q] * score_w[m * 2 * Dc + d] + ii[q] * score_w[m * 2 * Dc + Dc + d];
        cA += rr[q] * conf_w[m * 2 * Dc + d]  + ii[q] * conf_w[m * 2 * Dc + Dc + d];
        hA += rr[q] * halt_w[m * 2 * Dc + d]  + ii[q] * halt_w[m * 2 * Dc + Dc + d];
    }
    *(float4*)(ar + t * 4) = make_float4(rr[0], rr[1], rr[2], rr[3]);
    *(float4*)(ai + t * 4) = make_float4(ii[0], ii[1], ii[2], ii[3]);
    sA = blockSum128(sA); cA = blockSum128(cA); hA = blockSum128(hA);
    if (t == 0) {
        g_scratch[O_SCORE + row] = sA + score_b[m];
        g_scratch[O_CONF + row]  = sigm(cA + conf_b[m]);
        g_scratch[O_HALT + row]  = sigm(hA + halt_b[m]);
    }
}

// flat_in[b][e] = mean over S of sr/si (old state)
__global__ void k_flatin() {
    int i = blockIdx.x * 256 + threadIdx.x;   // 4096 total
    int b = i >> 10, e = i & 1023;
    const float* base = (e < Dc) ? (g_scratch + O_SR + (size_t)b * Sc * Dc + e)
                                 : (g_scratch + O_SI + (size_t)b * Sc * Dc + (e - Dc));
    float s = 0.f;
#pragma unroll 4
    for (int ss = 0; ss < Sc; ss++) s += base[(size_t)ss * Dc];
    g_scratch[O_FLAT + i] = s * (1.f / Sc);
}

// control softmax + ptr update; one block (128 thr) per batch
__global__ void k_ctrl(const float* __restrict__ cw, const float* __restrict__ cb) {
    const int b = blockIdx.x, t = threadIdx.x;
    const float* f = g_scratch + O_FLAT + b * 2 * Dc;
    float a0 = 0.f, a1 = 0.f, a2 = 0.f;
    for (int e = t; e < 2 * Dc; e += 128) {
        float fv = f[e];
        a0 += fv * cw[e * 3 + 0];
        a1 += fv * cw[e * 3 + 1];
        a2 += fv * cw[e * 3 + 2];
    }
    a0 = blockSum128(a0); a1 = blockSum128(a1); a2 = blockSum128(a2);
    a0 += cb[0]; a1 += cb[1]; a2 += cb[2];
    float mx = fmaxf(a0, fmaxf(a1, a2));
    float e0 = expf(a0 - mx), e1 = expf(a1 - mx), e2 = expf(a2 - mx);
    float is = 1.f / (e0 + e1 + e2);
    float push = e0 * is, pop = e1 * is, noop = e2 * is;
    if (t < Kc) {
        float* P = g_scratch + O_PTR + b * Kc;
        float pu = P[(t + Kc - 1) % Kc];
        float pd = P[(t + 1) % Kc];
        float pc = P[t];
        float np = push * pu + pop * pd + noop * pc;
        float s = np;
#pragma unroll
        for (int o = 16; o; o >>= 1) s += __shfl_xor_sync(0xffffffffu, s, o);
        np /= (s + EPSF);
        P[t] = np;
        g_scratch[O_WMASK + b * Kc + t] = push * pu;
    }
}

// mem update + read; 4096 threads over (b,e)
__global__ void k_memread() {
    int i = blockIdx.x * 256 + threadIdx.x;
    int b = i >> 10, e = i & 1023;
    float fv = g_scratch[O_FLAT + i];
    float racc = 0.f;
#pragma unroll
    for (int k = 0; k < Kc; k++) {
        float w = g_scratch[O_WMASK + b * Kc + k];
        size_t mi = O_MEM + ((size_t)(b * Kc + k)) * (2 * Dc) + e;
        float old = g_scratch[mi];
        float nm = fmaf(w, fv - old, old);          // w*fv + old*(1-w)
        g_scratch[mi] = nm;
        racc += nm * g_scratch[O_PTR + b * Kc + k];
    }
    g_scratch[O_READ + i] = racc;
}

// stack score/conf + halt mean + rem/coef update; block per batch
__global__ void k_sthalt(const float* __restrict__ stw, const float* __restrict__ stb,
                         const float* __restrict__ scw, const float* __restrict__ scb) {
    const int b = blockIdx.x, t = threadIdx.x;
    const float* r = g_scratch + O_READ + b * 2 * Dc;
    float s1 = 0.f, s2 = 0.f;
    for (int e = t; e < 2 * Dc; e += 128) { s1 += r[e] * stw[e]; s2 += r[e] * scw[e]; }
    float h = 0.f;
    for (int idx = t; idx < Mc * Sc; idx += 128)
        h += g_scratch[O_HALT + (idx >> 7) * NBS + b * Sc + (idx & 127)];
    s1 = blockSum128(s1); s2 = blockSum128(s2); h = blockSum128(h);
    if (t == 0) {
        g_scratch[O_STSC + b] = s1 + stb[0];
        g_scratch[O_STCF + b] = sigm(s2 + scb[0]);
        float p = h * (1.f / (Mc * Sc));
        float rm = g_scratch[O_REM + b];
        g_scratch[O_COEF + b] = p * rm;
        g_scratch[O_REM + b] = rm * (1.f - p);
    }
}

// module-softmax combine + state write + acc update; block per (b,s)
__global__ void k_combine() {
    const int bs = blockIdx.x;
    const int b = bs >> 7;
    float l[5];
#pragma unroll
    for (int m = 0; m < Mc; m++)
        l[m] = g_scratch[O_SCORE + m * NBS + bs] * g_scratch[O_CONF + m * NBS + bs];
    l[4] = g_scratch[O_STSC + b] * g_scratch[O_STCF + b];
    float mx = l[0];
#pragma unroll
    for (int m = 1; m < 5; m++) mx = fmaxf(mx, l[m]);
    float w[5], s = 0.f;
#pragma unroll
    for (int m = 0; m < 5; m++) { w[m] = expf(l[m] - mx); s += w[m]; }
    float is = 1.f / s;
#pragma unroll
    for (int m = 0; m < 5; m++) w[m] *= is;
    float cf = g_scratch[O_COEF + b];
    const int t = threadIdx.x;
    for (int d = t; d < Dc; d += 128) {
        float nr = w[4] * g_scratch[O_READ + b * 2 * Dc + d];
        float ni = w[4] * g_scratch[O_READ + b * 2 * Dc + Dc + d];
#pragma unroll
        for (int m = 0; m < Mc; m++) {
            nr += w[m] * g_scratch[O_PR + ((size_t)m * NBS + bs) * Dc + d];
            ni += w[m] * g_scratch[O_PI + ((size_t)m * NBS + bs) * Dc + d];
        }
        g_scratch[O_SR + (size_t)bs * Dc + d] = nr;
        g_scratch[O_SI + (size_t)bs * Dc + d] = ni;
        g_scratch[O_ACC + (size_t)bs * 2 * Dc + d]      += cf * nr;
        g_scratch[O_ACC + (size_t)bs * 2 * Dc + Dc + d] += cf * ni;
    }
}

// out = acc + rem * concat(sr, si)
__global__ void k_final(float* __restrict__ out) {
    int i = blockIdx.x * 256 + threadIdx.x;   // 524288
    int bs = i >> 10, e = i & 1023;
    int b = bs >> 7;
    float st = (e < Dc) ? g_scratch[O_SR + (size_t)bs * Dc + e]
                        : g_scratch[O_SI + (size_t)bs * Dc + (e - Dc)];
    out[i] = g_scratch[O_ACC + i] + g_scratch[O_REM + b] * st;
}

// ---------------------------------------------------------------------------
extern "C" void kernel_launch(void* const* d_in, const int* in_sizes, int n_in,
                              void* d_out, int out_size) {
    const float* xr        = (const float*)d_in[0];
    const float* xi        = (const float*)d_in[1];
    const float* Wl_r      = (const float*)d_in[2];
    const float* Wl_i      = (const float*)d_in[3];
    const float* Wq_r      = (const float*)d_in[4];
    const float* Wq_i      = (const float*)d_in[5];
    const float* Wk_r      = (const float*)d_in[6];
    const float* Wk_i      = (const float*)d_in[7];
    const float* Wv_r      = (const float*)d_in[8];
    const float* Wv_i      = (const float*)d_in[9];
    const float* ln_scale  = (const float*)d_in[10];
    const float* ln_shift  = (const float*)d_in[11];
    const float* mod_bias  = (const float*)d_in[12];
    const float* gate_mask = (const float*)d_in[13];
    const float* score_w   = (const float*)d_in[14];
    const float* score_b   = (const float*)d_in[15];
    const float* conf_w    = (const float*)d_in[16];
    const float* conf_b    = (const float*)d_in[17];
    const float* halt_w    = (const float*)d_in[18];
    const float* halt_b    = (const float*)d_in[19];
    const float* ctrl_w    = (const float*)d_in[20];
    const float* ctrl_b    = (const float*)d_in[21];
    const float* st_score_w= (const float*)d_in[22];
    const float* st_score_b= (const float*)d_in[23];
    const float* st_conf_w = (const float*)d_in[24];
    const float* st_conf_b = (const float*)d_in[25];

    float* base;
    cudaGetSymbolAddress((void**)&base, g_scratch);
    float* cr = base + O_CR; float* ci = base + O_CI;
    float* zr = base + O_ZR; float* zi = base + O_ZI;
    float* qr = base + O_QR; float* qi = base + O_QI;
    float* kr = base + O_KR; float* ki = base + O_KI;
    float* vr = base + O_VR; float* vi = base + O_VI;
    float* at = base + O_AT;
    float* pr = base + O_PR; float* pi = base + O_PI;

    k_init<<<2048, 256>>>(xr, xi, gate_mask);

    for (int step = 0; step < NSTEPS; step++) {
        k_pre<<<NBSD / 256, 256>>>(xr, xi);
        // z = Wl projection of c (A shared across modules)
        gemm_nt<false, true><<<dim3(8, 8, Mc), 256>>>(
            cr, ci, 0, Wl_r, Wl_i, Dc * Dc, zr, zi, NBSD, Dc, Dc, 1.f);
        k_norm<<<NMBS, 128>>>(ln_scale, ln_shift, mod_bias);
        // Q, K, V projections (per-module A)
        gemm_nt<false, true><<<dim3(8, 8, Mc), 256>>>(
            zr, zi, NBSD, Wq_r, Wq_i, Dc * Dc, qr, qi, NBSD, Dc, Dc, 1.f);
        gemm_nt<false, true><<<dim3(8, 8, Mc), 256>>>(
            zr, zi, NBSD, Wk_r, Wk_i, Dc * Dc, kr, ki, NBSD, Dc, Dc, 1.f);
        gemm_nt<false, true><<<dim3(8, 8, Mc), 256>>>(
            zr, zi, NBSD, Wv_r, Wv_i, Dc * Dc, vr, vi, NBSD, Dc, Dc, 1.f);
        // logits = SCALE * (qr.kr^T + qi.ki^T)
        gemm_nt<true, false><<<dim3(2, 2, Mc * Bc), 256>>>(
            qr, qi, Sc * Dc, kr, ki, Sc * Dc, at, at, Sc * Sc, Dc, Sc, SCALEF);
        k_softmax<<<NMBS, 128>>>();
        gemm_av<<<dim3(8, 2, Mc * Bc), 256>>>(at, vr, vi, pr, pi);
        k_gatescore<<<NMBS, 128>>>(score_w, score_b, conf_w, conf_b, halt_w, halt_b);
        k_flatin<<<16, 256>>>();
        k_ctrl<<<Bc, 128>>>(ctrl_w, ctrl_b);
        k_memread<<<16, 256>>>();
        k_sthalt<<<Bc, 128>>>(st_score_w, st_score_b, st_conf_w, st_conf_b);
        k_combine<<<NBS, 128>>>();
    }
    k_final<<<2048, 256>>>((float*)d_out);
}

// round 3
// speedup vs baseline: 1.8335x; 1.8335x over previous
#include <cuda_runtime.h>
#include <cuda_bf16.h>
#include <math.h>

// ---------------------------------------------------------------------------
// ComplexRecurrentModel on GB300 (sm_103 non-'a' PTX target!).
// tcgen05 is unavailable (harness PTX target lacks the 'a' feature suffix),
// so tensor work goes through mma.sync.m16n8k16 bf16 (sm_80+ baseline PTX).
// Complex GEMMs reformulated as real GEMMs on [re|im] 1024-wide layout.
// Split precision: x = h + l (bf16 each); C = Ah*Bh + Ah*Bl + Al*Bh with
// fp32 accumulation -> ~1e-5 per-GEMM relative error.
// ---------------------------------------------------------------------------

#define Bc 4
#define Sc 128
#define Dc 512
#define Mc 4
#define Kc 32
#define NSTEPS 16
#define EPSF 1e-6f
#define SCALEF 0.044194173824159216f   // 512^-0.5

constexpr int ROWS = Bc * Sc;              // 512
constexpr int E2 = 2 * Dc;                 // 1024
constexpr int NBS = Bc * Sc;               // 512
constexpr int NMBS = Mc * NBS;             // 2048
constexpr size_t WELEMS = (size_t)4 * Mc * E2 * E2;   // 16,777,216
constexpr size_t WTYPE  = (size_t)Mc * E2 * E2;       // 4,194,304 per type
constexpr size_t WMOD   = (size_t)E2 * E2;            // 1,048,576 per module

// ---- device buffers -------------------------------------------------------
__device__ __align__(256) __nv_bfloat16 g_WPH[WELEMS];
__device__ __align__(256) __nv_bfloat16 g_WPL[WELEMS];
__device__ __align__(256) __nv_bfloat16 g_Ch[ROWS * E2], g_Cl[ROWS * E2];
__device__ __align__(256) float         g_Z [Mc * ROWS * E2];
__device__ __align__(256) __nv_bfloat16 g_Zh[Mc * ROWS * E2], g_Zl[Mc * ROWS * E2];
__device__ __align__(256) __nv_bfloat16 g_Qh[Mc * ROWS * E2], g_Ql[Mc * ROWS * E2];
__device__ __align__(256) __nv_bfloat16 g_Kh[Mc * ROWS * E2], g_Kl[Mc * ROWS * E2];
__device__ __align__(256) __nv_bfloat16 g_Vth[16 * E2 * Sc], g_Vtl[16 * E2 * Sc]; // [z][d][s]
__device__ __align__(256) float         g_logits[16 * Sc * Sc];
__device__ __align__(256) __nv_bfloat16 g_ATh[16 * Sc * Sc], g_ATl[16 * Sc * Sc];
__device__ __align__(256) float         g_P [Mc * ROWS * E2];
__device__ __align__(256) float g_sr[ROWS * Dc], g_si[ROWS * Dc];
__device__ __align__(256) float g_acc[ROWS * E2];
__device__ __align__(256) float g_mem[Bc * Kc * E2];
__device__ __align__(256) float g_ptrst[Bc * Kc];
__device__ __align__(256) float g_score[NMBS], g_conf[NMBS], g_halt[NMBS];
__device__ __align__(256) float g_flat[Bc * E2], g_read[Bc * E2];
__device__ __align__(256) float g_wmask[Bc * Kc];
__device__ __align__(256) float g_gate[Mc * Dc];
__device__ __align__(256) float g_rem[16], g_stsc[16], g_stcf[16], g_coef[16];

// ---------------------------------------------------------------------------
// helpers
// ---------------------------------------------------------------------------
__device__ __forceinline__ unsigned smem_u32(const void* p) {
    unsigned a;
    asm("{ .reg .u64 t; cvta.to.shared.u64 t, %1; cvt.u32.u64 %0, t; }" : "=r"(a) : "l"(p));
    return a;
}
__device__ __forceinline__ void sts16(unsigned a, uint4 v) {
    asm volatile("st.shared.v4.b32 [%0], {%1, %2, %3, %4};"
                 :: "r"(a), "r"(v.x), "r"(v.y), "r"(v.z), "r"(v.w) : "memory");
}
__device__ __forceinline__ void ldmat_x4(unsigned (&r)[4], unsigned addr) {
    asm volatile("ldmatrix.sync.aligned.m8n8.x4.shared.b16 {%0,%1,%2,%3}, [%4];"
                 : "=r"(r[0]), "=r"(r[1]), "=r"(r[2]), "=r"(r[3]) : "r"(addr));
}
__device__ __forceinline__ void mma16816(float (&c)[4], const unsigned* a, const unsigned* b) {
    asm volatile("mma.sync.aligned.m16n8k16.row.col.f32.bf16.bf16.f32 "
                 "{%0,%1,%2,%3}, {%4,%5,%6,%7}, {%8,%9}, {%0,%1,%2,%3};"
                 : "+f"(c[0]), "+f"(c[1]), "+f"(c[2]), "+f"(c[3])
                 : "r"(a[0]), "r"(a[1]), "r"(a[2]), "r"(a[3]), "r"(b[0]), "r"(b[1]));
}
__device__ __forceinline__ unsigned swz128(unsigned off) { return off ^ ((off >> 3) & 0x70); }

// ---------------------------------------------------------------------------
// mma.sync GEMM: D[z][row][col] = sum_k A[z][row][k] * B[z][col][k]
// A, B split into (h, l) bf16; 3 products accumulated in fp32 registers.
// MODE 0: fp32 out ; MODE 1: split-bf16 out ; MODE 2: split-bf16 transposed
//  (V mode: out[((z*4+b)*1024 + col)*128 + s], b=row>>7, s=row&127)
// MODE 3: fp32 atomicAdd out (for split-K)
// KSPLIT: blockIdx.y indexes a K-slice of length ktot (row0 = 0)
// ---------------------------------------------------------------------------
constexpr int GEMM_SMEM = 65536;   // 4 x 16KB tiles (Ah, Al, Bh, Bl)

template <int MODE, bool KSPLIT>
__global__ void __launch_bounds__(256, 1) gemm_mma(
    const __nv_bfloat16* __restrict__ Ah, const __nv_bfloat16* __restrict__ Al,
    int aK, size_t aZ,
    const __nv_bfloat16* __restrict__ Bh, const __nv_bfloat16* __restrict__ Bl,
    int bK, size_t bZ,
    float* __restrict__ outF, __nv_bfloat16* __restrict__ outH, __nv_bfloat16* __restrict__ outL,
    int ldOut, size_t outZ, int ktot)
{
    extern __shared__ char smem_raw[];
    const unsigned sbase = smem_u32(smem_raw);
    const unsigned sA[2] = { sbase, sbase + 16384u };          // Ah, Al
    const unsigned sB[2] = { sbase + 32768u, sbase + 49152u }; // Bh, Bl

    const int tid = threadIdx.x;
    const int wid = tid >> 5, lane = tid & 31;
    const int z = blockIdx.z;
    const int col0 = blockIdx.x * 128;
    const int row0 = KSPLIT ? 0 : blockIdx.y * 128;
    const int kbase = KSPLIT ? blockIdx.y * ktot : 0;

    const int warpM = (wid & 3) * 32, warpN = (wid >> 2) * 64;

    const __nv_bfloat16* aP[2] = { Ah + (size_t)z * aZ + (size_t)row0 * aK + kbase,
                                   Al + (size_t)z * aZ + (size_t)row0 * aK + kbase };
    const __nv_bfloat16* bP[2] = { Bh + (size_t)z * bZ + (size_t)col0 * bK + kbase,
                                   Bl + (size_t)z * bZ + (size_t)col0 * bK + kbase };

    float acc[2][8][4];
#pragma unroll
    for (int mt = 0; mt < 2; mt++)
#pragma unroll
        for (int nt = 0; nt < 8; nt++)
#pragma unroll
            for (int q = 0; q < 4; q++) acc[mt][nt][q] = 0.f;

    // per-lane ldmatrix geometry
    const int lmat = lane >> 3, lrow = lane & 7;
    // A: mat -> m_off = (mat&1)*8, k_off = (mat>>1)*8
    const int a_m = (lmat & 1) * 8 + lrow;
    const int a_k = (lmat >> 1) * 8;
    // B: mat -> n_off = (mat>>1)*8, k_off = (mat&1)*8
    const int b_n = (lmat >> 1) * 8 + lrow;
    const int b_k = (lmat & 1) * 8;

    const int nchunk = ktot >> 6;
    for (int ch = 0; ch < nchunk; ch++) {
        const int k0 = ch << 6;
        // stage 4 tiles of [128 rows x 64 bf16] (SW128, 128B rows)
#pragma unroll
        for (int hl = 0; hl < 2; hl++) {
#pragma unroll
            for (int it = 0; it < 4; it++) {
                int idx = it * 256 + tid;            // 0..1023
                int r = idx >> 3, c = (idx & 7) * 8; // c in bf16 elems
                unsigned so = swz128((unsigned)(r * 128 + c * 2));
                uint4 va = *(const uint4*)(aP[hl] + (size_t)r * aK + k0 + c);
                uint4 vb = *(const uint4*)(bP[hl] + (size_t)r * bK + k0 + c);
                sts16(sA[hl] + so, va);
                sts16(sB[hl] + so, vb);
            }
        }
        __syncthreads();

#pragma unroll
        for (int ks = 0; ks < 4; ks++) {
            unsigned ah[2][4], al[2][4];
#pragma unroll
            for (int mt = 0; mt < 2; mt++) {
                int m = warpM + mt * 16 + a_m;
                int kk = ks * 16 + a_k;
                unsigned off = swz128((unsigned)(m * 128 + kk * 2));
                ldmat_x4(ah[mt], sA[0] + off);
                ldmat_x4(al[mt], sA[1] + off);
            }
            unsigned bh[8][2], bl[8][2];
#pragma unroll
            for (int np = 0; np < 4; np++) {
                int n = warpN + np * 16 + b_n;
                int kk = ks * 16 + b_k;
                unsigned off = swz128((unsigned)(n * 128 + kk * 2));
                unsigned rh[4], rl[4];
                ldmat_x4(rh, sB[0] + off);
                ldmat_x4(rl, sB[1] + off);
                bh[2 * np][0] = rh[0]; bh[2 * np][1] = rh[1];
                bh[2 * np + 1][0] = rh[2]; bh[2 * np + 1][1] = rh[3];
                bl[2 * np][0] = rl[0]; bl[2 * np][1] = rl[1];
                bl[2 * np + 1][0] = rl[2]; bl[2 * np + 1][1] = rl[3];
            }
#pragma unroll
            for (int mt = 0; mt < 2; mt++)
#pragma unroll
                for (int nt = 0; nt < 8; nt++) {
                    mma16816(acc[mt][nt], ah[mt], bh[nt]);
                    mma16816(acc[mt][nt], ah[mt], bl[nt]);
                    mma16816(acc[mt][nt], al[mt], bh[nt]);
                }
        }
        __syncthreads();
    }

    // epilogue: C frag lane l -> rows (l/4, l/4+8), cols (l%4)*2 + {0,1}
    const int erow = lane >> 2, ecol = (lane & 3) * 2;
#pragma unroll
    for (int mt = 0; mt < 2; mt++) {
#pragma unroll
        for (int nt = 0; nt < 8; nt++) {
            const float* c = acc[mt][nt];
#pragma unroll
            for (int half = 0; half < 2; half++) {
                int rowG = row0 + warpM + mt * 16 + erow + half * 8;
                int colG = col0 + warpN + nt * 8 + ecol;
                float v0 = c[half * 2 + 0], v1 = c[half * 2 + 1];
                if (MODE == 0) {
                    float* o = outF + (size_t)z * outZ + (size_t)rowG * ldOut + colG;
                    o[0] = v0; o[1] = v1;
                } else if (MODE == 3) {
                    float* o = outF + (size_t)z * outZ + (size_t)rowG * ldOut + colG;
                    atomicAdd(o + 0, v0);
                    atomicAdd(o + 1, v1);
                } else if (MODE == 1) {
                    size_t base = (size_t)z * outZ + (size_t)rowG * ldOut + colG;
                    __nv_bfloat16 h0 = __float2bfloat16(v0);
                    __nv_bfloat16 h1 = __float2bfloat16(v1);
                    outH[base + 0] = h0; outL[base + 0] = __float2bfloat16(v0 - __bfloat162float(h0));
                    outH[base + 1] = h1; outL[base + 1] = __float2bfloat16(v1 - __bfloat162float(h1));
                } else {
                    const int b = rowG >> 7, s = rowG & 127;
                    __nv_bfloat16 h0 = __float2bfloat16(v0);
                    __nv_bfloat16 h1 = __float2bfloat16(v1);
                    size_t o0 = ((size_t)(z * 4 + b) * E2 + colG) * Sc + s;
                    outH[o0] = h0; outL[o0] = __float2bfloat16(v0 - __bfloat162float(h0));
                    size_t o1 = o0 + Sc;
                    outH[o1] = h1; outL[o1] = __float2bfloat16(v1 - __bfloat162float(h1));
                }
            }
        }
    }
}

// ---------------------------------------------------------------------------
// reductions
// ---------------------------------------------------------------------------
__device__ __forceinline__ float sigm(float x) { return 1.f / (1.f + expf(-x)); }

__device__ __forceinline__ float blockSum128(float v) {
    __shared__ float sh[4];
    int lane = threadIdx.x & 31, w = threadIdx.x >> 5;
#pragma unroll
    for (int o = 16; o; o >>= 1) v += __shfl_xor_sync(0xffffffffu, v, o);
    if (lane == 0) sh[w] = v;
    __syncthreads();
    float r = sh[0] + sh[1] + sh[2] + sh[3];
    __syncthreads();
    return r;
}
__device__ __forceinline__ float blockMax128(float v) {
    __shared__ float sh[4];
    int lane = threadIdx.x & 31, w = threadIdx.x >> 5;
#pragma unroll
    for (int o = 16; o; o >>= 1) v = fmaxf(v, __shfl_xor_sync(0xffffffffu, v, o));
    if (lane == 0) sh[w] = v;
    __syncthreads();
    float r = fmaxf(fmaxf(sh[0], sh[1]), fmaxf(sh[2], sh[3]));
    __syncthreads();
    return r;
}

// ---------------------------------------------------------------------------
// elementwise / small kernels
// ---------------------------------------------------------------------------
__global__ void k_pack(const float* __restrict__ Wl_r, const float* __restrict__ Wl_i,
                       const float* __restrict__ Wq_r, const float* __restrict__ Wq_i,
                       const float* __restrict__ Wk_r, const float* __restrict__ Wk_i,
                       const float* __restrict__ Wv_r, const float* __restrict__ Wv_i) {
    size_t idx = (size_t)blockIdx.x * 256 + threadIdx.x;  // 16,777,216
    int k = (int)(idx & 1023), j = (int)((idx >> 10) & 1023);
    int m = (int)((idx >> 20) & 3), t = (int)(idx >> 22);
    const float* Wr; const float* Wi;
    if (t == 0) { Wr = Wl_r; Wi = Wl_i; }
    else if (t == 1) { Wr = Wq_r; Wi = Wq_i; }
    else if (t == 2) { Wr = Wk_r; Wi = Wk_i; }
    else { Wr = Wv_r; Wi = Wv_i; }
    int jj = j & 511, kk = k & 511;
    size_t base = (size_t)m * Dc * Dc + (size_t)jj * Dc + kk;
    float v;
    if (j < Dc) v = (k < Dc) ? Wr[base] : -Wi[base];
    else        v = (k < Dc) ?  Wi[base] :  Wr[base];
    __nv_bfloat16 h = __float2bfloat16(v);
    g_WPH[idx] = h;
    g_WPL[idx] = __float2bfloat16(v - __bfloat162float(h));
}

__global__ void k_init(const float* __restrict__ xr, const float* __restrict__ xi,
                       const float* __restrict__ gate_mask) {
    int i = blockIdx.x * 256 + threadIdx.x;   // 524288
    if (i < ROWS * Dc) { g_sr[i] = xr[i]; g_si[i] = xi[i]; }
    if (i < ROWS * E2) g_acc[i] = 0.f;
    if (i < Bc * Kc * E2) g_mem[i] = 0.f;
    if (i < Bc * Kc) g_ptrst[i] = (i % Kc == 0) ? 1.f : 0.f;
    if (i < Mc * Dc) g_gate[i] = sigm(gate_mask[i]);
    if (i < Bc) g_rem[i] = 1.f;
}

// C = 0.5*(x + s) packed [bs][1024] as split bf16; also zero attn logits
__global__ void k_pre(const float* __restrict__ xr, const float* __restrict__ xi) {
    int i = blockIdx.x * 256 + threadIdx.x;   // ROWS*E2 = 524288
    int bs = i >> 10, e = i & 1023;
    float v;
    if (e < Dc) v = 0.5f * (xr[bs * Dc + e] + g_sr[bs * Dc + e]);
    else        v = 0.5f * (xi[bs * Dc + e - Dc] + g_si[bs * Dc + e - Dc]);
    __nv_bfloat16 h = __float2bfloat16(v);
    g_Ch[i] = h;
    g_Cl[i] = __float2bfloat16(v - __bfloat162float(h));
    if (i < 16 * Sc * Sc) g_logits[i] = 0.f;
}

// magnitude LN + phase + modReLU on Z [m][512][1024]; writes split bf16
__global__ void k_norm(const float* __restrict__ ln_scale,
                       const float* __restrict__ ln_shift,
                       const float* __restrict__ mod_bias) {
    const int row = blockIdx.x;            // m*512 + bs
    const int m = row >> 9;
    const float* zp = g_Z + (size_t)row * E2;
    const int t = threadIdx.x;             // 128 thr, 4 complex each
    float vr[4], vi[4], mg[4];
    float s = 0.f, ss = 0.f;
#pragma unroll
    for (int q = 0; q < 4; q++) {
        int d = t * 4 + q;
        vr[q] = zp[d]; vi[q] = zp[Dc + d];
        mg[q] = sqrtf(vr[q] * vr[q] + vi[q] * vi[q]) + EPSF;
        s += mg[q]; ss += mg[q] * mg[q];
    }
    float sum = blockSum128(s);
    float sumsq = blockSum128(ss);
    float mean = sum * (1.f / Dc);
    float var = (sumsq - (float)Dc * mean * mean) * (1.f / (Dc - 1));
    float rstd = rsqrtf(var + EPSF);
    __nv_bfloat16* oh = g_Zh + (size_t)row * E2;
    __nv_bfloat16* ol = g_Zl + (size_t)row * E2;
#pragma unroll
    for (int q = 0; q < 4; q++) {
        int d = t * 4 + q;
        float nm = (mg[q] - mean) * rstd * ln_scale[m * Dc + d] + ln_shift[m * Dc + d];
        float hyp = sqrtf(vr[q] * vr[q] + vi[q] * vi[q]);
        float c, sn;
        if (hyp > 0.f) { float ih = 1.f / hyp; c = vr[q] * ih; sn = vi[q] * ih; }
        else { c = 1.f; sn = 0.f; }
        float zr2 = nm * c, zi2 = nm * sn;
        float nrm = fabsf(nm) + EPSF;
        float sc = fmaxf(nrm + mod_bias[m * Dc + d], 0.f) / nrm;
        float fr = zr2 * sc, fi = zi2 * sc;
        __nv_bfloat16 hr = __float2bfloat16(fr);
        __nv_bfloat16 hi = __float2bfloat16(fi);
        oh[d] = hr;       ol[d] = __float2bfloat16(fr - __bfloat162float(hr));
        oh[Dc + d] = hi;  ol[Dc + d] = __float2bfloat16(fi - __bfloat162float(hi));
    }
}

// softmax over t of logits*SCALE; writes attn split bf16
__global__ void k_softmax() {
    const int row = blockIdx.x;            // 16*128
    const float* p = g_logits + (size_t)row * Sc;
    float v = p[threadIdx.x] * SCALEF;
    float mx = blockMax128(v);
    float e = expf(v - mx);
    float su = blockSum128(e);
    float a = e / su;
    __nv_bfloat16 h = __float2bfloat16(a);
    g_ATh[(size_t)row * Sc + threadIdx.x] = h;
    g_ATl[(size_t)row * Sc + threadIdx.x] = __float2bfloat16(a - __bfloat162float(h));
}

// gate + score/conf/halt dots; P [m][512][1024] gated in place
__global__ void k_gatescore(const float* __restrict__ score_w, const float* __restrict__ score_b,
                            const float* __restrict__ conf_w,  const float* __restrict__ conf_b,
                            const float* __restrict__ halt_w,  const float* __restrict__ halt_b) {
    const int row = blockIdx.x;            // m*512 + bs
    const int m = row >> 9;
    float* pp = g_P + (size_t)row * E2;
    const int t = threadIdx.x;
    float sA = 0.f, cA = 0.f, hA = 0.f;
    float rr[4], ii[4];
#pragma unroll
    for (int q = 0; q < 4; q++) {
        int d = t * 4 + q;
        float g = g_gate[m * Dc + d];
        rr[q] = pp[d] * g;
        ii[q] = pp[Dc + d] * g;
        sA += rr[q] * score_w[m * E2 + d] + ii[q] * score_w[m * E2 + Dc + d];
        cA += rr[q] * conf_w[m * E2 + d]  + ii[q] * conf_w[m * E2 + Dc + d];
        hA += rr[q] * halt_w[m * E2 + d]  + ii[q] * halt_w[m * E2 + Dc + d];
    }
#pragma unroll
    for (int q = 0; q < 4; q++) {
        int d = t * 4 + q;
        pp[d] = rr[q]; pp[Dc + d] = ii[q];
    }
    sA = blockSum128(sA); cA = blockSum128(cA); hA = blockSum128(hA);
    if (t == 0) {
        g_score[row] = sA + score_b[m];
        g_conf[row]  = sigm(cA + conf_b[m]);
        g_halt[row]  = sigm(hA + halt_b[m]);
    }
}

__global__ void k_flatin() {
    int i = blockIdx.x * 256 + threadIdx.x;   // 4096
    int b = i >> 10, e = i & 1023;
    const float* base = (e < Dc) ? (g_sr + (size_t)b * Sc * Dc + e)
                                 : (g_si + (size_t)b * Sc * Dc + (e - Dc));
    float s = 0.f;
#pragma unroll 4
    for (int ss = 0; ss < Sc; ss++) s += base[(size_t)ss * Dc];
    g_flat[i] = s * (1.f / Sc);
}

__global__ void k_ctrl(const float* __restrict__ cw, const float* __restrict__ cb) {
    const int b = blockIdx.x, t = threadIdx.x;
    const float* f = g_flat + b * E2;
    float a0 = 0.f, a1 = 0.f, a2 = 0.f;
    for (int e = t; e < E2; e += 128) {
        float fv = f[e];
        a0 += fv * cw[e * 3 + 0];
        a1 += fv * cw[e * 3 + 1];
        a2 += fv * cw[e * 3 + 2];
    }
    a0 = blockSum128(a0); a1 = blockSum128(a1); a2 = blockSum128(a2);
    a0 += cb[0]; a1 += cb[1]; a2 += cb[2];
    float mx = fmaxf(a0, fmaxf(a1, a2));
    float e0 = expf(a0 - mx), e1 = expf(a1 - mx), e2 = expf(a2 - mx);
    float is = 1.f / (e0 + e1 + e2);
    float push = e0 * is, pop = e1 * is, noop = e2 * is;
    if (t < Kc) {
        float* P = g_ptrst + b * Kc;
        float pu = P[(t + Kc - 1) % Kc];
        float pd = P[(t + 1) % Kc];
        float pc = P[t];
        float np = push * pu + pop * pd + noop * pc;
        float s = np;
#pragma unroll
        for (int o = 16; o; o >>= 1) s += __shfl_xor_sync(0xffffffffu, s, o);
        np /= (s + EPSF);
        P[t] = np;
        g_wmask[b * Kc + t] = push * pu;
    }
}

__global__ void k_memread() {
    int i = blockIdx.x * 256 + threadIdx.x;   // 4096
    int b = i >> 10, e = i & 1023;
    float fv = g_flat[i];
    float racc = 0.f;
#pragma unroll
    for (int k = 0; k < Kc; k++) {
        float w = g_wmask[b * Kc + k];
        size_t mi = ((size_t)(b * Kc + k)) * E2 + e;
        float old = g_mem[mi];
        float nm = fmaf(w, fv - old, old);
        g_mem[mi] = nm;
        racc += nm * g_ptrst[b * Kc + k];
    }
    g_read[i] = racc;
}

__global__ void k_sthalt(const float* __restrict__ stw, const float* __restrict__ stb,
                         const float* __restrict__ scw, const float* __restrict__ scb) {
    const int b = blockIdx.x, t = threadIdx.x;
    const float* r = g_read + b * E2;
    float s1 = 0.f, s2 = 0.f;
    for (int e = t; e < E2; e += 128) { s1 += r[e] * stw[e]; s2 += r[e] * scw[e]; }
    float h = 0.f;
    for (int idx = t; idx < Mc * Sc; idx += 128)
        h += g_halt[(idx >> 7) * NBS + b * Sc + (idx & 127)];
    s1 = blockSum128(s1); s2 = blockSum128(s2); h = blockSum128(h);
    if (t == 0) {
        g_stsc[b] = s1 + stb[0];
        g_stcf[b] = sigm(s2 + scb[0]);
        float p = h * (1.f / (Mc * Sc));
        float rm = g_rem[b];
        g_coef[b] = p * rm;
        g_rem[b] = rm * (1.f - p);
    }
}

__global__ void k_combine() {
    const int bs = blockIdx.x;
    const int b = bs >> 7;
    float l[5];
#pragma unroll
    for (int m = 0; m < Mc; m++)
        l[m] = g_score[m * NBS + bs] * g_conf[m * NBS + bs];
    l[4] = g_stsc[b] * g_stcf[b];
    float mx = l[0];
#pragma unroll
    for (int m = 1; m < 5; m++) mx = fmaxf(mx, l[m]);
    float w[5], s = 0.f;
#pragma unroll
    for (int m = 0; m < 5; m++) { w[m] = expf(l[m] - mx); s += w[m]; }
    float is = 1.f / s;
#pragma unroll
    for (int m = 0; m < 5; m++) w[m] *= is;
    float cf = g_coef[b];
    const int t = threadIdx.x;
    for (int d = t; d < Dc; d += 128) {
        float nr = w[4] * g_read[b * E2 + d];
        float ni = w[4] * g_read[b * E2 + Dc + d];
#pragma unroll
        for (int m = 0; m < Mc; m++) {
            nr += w[m] * g_P[((size_t)m * NBS + bs) * E2 + d];
            ni += w[m] * g_P[((size_t)m * NBS + bs) * E2 + Dc + d];
        }
        g_sr[(size_t)bs * Dc + d] = nr;
        g_si[(size_t)bs * Dc + d] = ni;
        g_acc[(size_t)bs * E2 + d]      += cf * nr;
        g_acc[(size_t)bs * E2 + Dc + d] += cf * ni;
    }
}

__global__ void k_final(float* __restrict__ out) {
    int i = blockIdx.x * 256 + threadIdx.x;   // 524288
    int bs = i >> 10, e = i & 1023;
    int b = bs >> 7;
    float st = (e < Dc) ? g_sr[(size_t)bs * Dc + e]
                        : g_si[(size_t)bs * Dc + (e - Dc)];
    out[i] = g_acc[i] + g_rem[b] * st;
}

// ---------------------------------------------------------------------------
extern "C" void kernel_launch(void* const* d_in, const int* in_sizes, int n_in,
                              void* d_out, int out_size) {
    const float* xr        = (const float*)d_in[0];
    const float* xi        = (const float*)d_in[1];
    const float* Wl_r      = (const float*)d_in[2];
    const float* Wl_i      = (const float*)d_in[3];
    const float* Wq_r      = (const float*)d_in[4];
    const float* Wq_i      = (const float*)d_in[5];
    const float* Wk_r      = (const float*)d_in[6];
    const float* Wk_i      = (const float*)d_in[7];
    const float* Wv_r      = (const float*)d_in[8];
    const float* Wv_i      = (const float*)d_in[9];
    const float* ln_scale  = (const float*)d_in[10];
    const float* ln_shift  = (const float*)d_in[11];
    const float* mod_bias  = (const float*)d_in[12];
    const float* gate_mask = (const float*)d_in[13];
    const float* score_w   = (const float*)d_in[14];
    const float* score_b   = (const float*)d_in[15];
    const float* conf_w    = (const float*)d_in[16];
    const float* conf_b    = (const float*)d_in[17];
    const float* halt_w    = (const float*)d_in[18];
    const float* halt_b    = (const float*)d_in[19];
    const float* ctrl_w    = (const float*)d_in[20];
    const float* ctrl_b    = (const float*)d_in[21];
    const float* st_score_w= (const float*)d_in[22];
    const float* st_score_b= (const float*)d_in[23];
    const float* st_conf_w = (const float*)d_in[24];
    const float* st_conf_b = (const float*)d_in[25];

    cudaFuncSetAttribute(gemm_mma<0,false>, cudaFuncAttributeMaxDynamicSharedMemorySize, GEMM_SMEM);
    cudaFuncSetAttribute(gemm_mma<1,false>, cudaFuncAttributeMaxDynamicSharedMemorySize, GEMM_SMEM);
    cudaFuncSetAttribute(gemm_mma<2,false>, cudaFuncAttributeMaxDynamicSharedMemorySize, GEMM_SMEM);
    cudaFuncSetAttribute(gemm_mma<3,true>,  cudaFuncAttributeMaxDynamicSharedMemorySize, GEMM_SMEM);

    __nv_bfloat16 *WPH, *WPL, *Ch, *Cl, *Zh, *Zl, *Qh, *Ql, *Kh, *Kl, *Vth, *Vtl, *ATh, *ATl;
    float *Z, *LG, *P;
    cudaGetSymbolAddress((void**)&WPH, g_WPH);
    cudaGetSymbolAddress((void**)&WPL, g_WPL);
    cudaGetSymbolAddress((void**)&Ch, g_Ch);
    cudaGetSymbolAddress((void**)&Cl, g_Cl);
    cudaGetSymbolAddress((void**)&Z, g_Z);
    cudaGetSymbolAddress((void**)&Zh, g_Zh);
    cudaGetSymbolAddress((void**)&Zl, g_Zl);
    cudaGetSymbolAddress((void**)&Qh, g_Qh);
    cudaGetSymbolAddress((void**)&Ql, g_Ql);
    cudaGetSymbolAddress((void**)&Kh, g_Kh);
    cudaGetSymbolAddress((void**)&Kl, g_Kl);
    cudaGetSymbolAddress((void**)&Vth, g_Vth);
    cudaGetSymbolAddress((void**)&Vtl, g_Vtl);
    cudaGetSymbolAddress((void**)&LG, g_logits);
    cudaGetSymbolAddress((void**)&ATh, g_ATh);
    cudaGetSymbolAddress((void**)&ATl, g_ATl);
    cudaGetSymbolAddress((void**)&P, g_P);

    k_pack<<<65536, 256>>>(Wl_r, Wl_i, Wq_r, Wq_i, Wk_r, Wk_i, Wv_r, Wv_i);
    k_init<<<2048, 256>>>(xr, xi, gate_mask);

    for (int step = 0; step < NSTEPS; step++) {
        k_pre<<<ROWS * E2 / 256, 256>>>(xr, xi);
        // Z = C x WlP  (A shared over modules)
        gemm_mma<0,false><<<dim3(8, 4, Mc), 256, GEMM_SMEM>>>(
            Ch, Cl, E2, 0,
            WPH + 0 * WTYPE, WPL + 0 * WTYPE, E2, WMOD,
            Z, nullptr, nullptr, E2, (size_t)ROWS * E2, E2);
        k_norm<<<NMBS, 128>>>(ln_scale, ln_shift, mod_bias);
        // Q, K (split-bf16 out), V (transposed split-bf16 out)
        gemm_mma<1,false><<<dim3(8, 4, Mc), 256, GEMM_SMEM>>>(
            Zh, Zl, E2, (size_t)ROWS * E2,
            WPH + 1 * WTYPE, WPL + 1 * WTYPE, E2, WMOD,
            nullptr, Qh, Ql, E2, (size_t)ROWS * E2, E2);
        gemm_mma<1,false><<<dim3(8, 4, Mc), 256, GEMM_SMEM>>>(
            Zh, Zl, E2, (size_t)ROWS * E2,
            WPH + 2 * WTYPE, WPL + 2 * WTYPE, E2, WMOD,
            nullptr, Kh, Kl, E2, (size_t)ROWS * E2, E2);
        gemm_mma<2,false><<<dim3(8, 4, Mc), 256, GEMM_SMEM>>>(
            Zh, Zl, E2, (size_t)ROWS * E2,
            WPH + 3 * WTYPE, WPL + 3 * WTYPE, E2, WMOD,
            nullptr, Vth, Vtl, 0, 0, E2);
        // logits[z=(m*4+b)][s][t] = Q . K^T  (split-K=4, atomic accumulate)
        gemm_mma<3,true><<<dim3(1, 4, 16), 256, GEMM_SMEM>>>(
            Qh, Ql, E2, (size_t)Sc * E2,
            Kh, Kl, E2, (size_t)Sc * E2,
            LG, nullptr, nullptr, Sc, (size_t)Sc * Sc, 256);
        k_softmax<<<16 * Sc, 128>>>();
        // P[z][s][d] = attn . Vt^T   (K = 128)
        gemm_mma<0,false><<<dim3(8, 1, 16), 256, GEMM_SMEM>>>(
            ATh, ATl, Sc, (size_t)Sc * Sc,
            Vth, Vtl, Sc, (size_t)E2 * Sc,
            P, nullptr, nullptr, E2, (size_t)Sc * E2, Sc);
        k_gatescore<<<NMBS, 128>>>(score_w, score_b, conf_w, conf_b, halt_w, halt_b);
        k_flatin<<<16, 256>>>();
        k_ctrl<<<Bc, 128>>>(ctrl_w, ctrl_b);
        k_memread<<<16, 256>>>();
        k_sthalt<<<Bc, 128>>>(st_score_w, st_score_b, st_conf_w, st_conf_b);
        k_combine<<<NBS, 128>>>();
    }
    k_final<<<2048, 256>>>((float*)d_out);
}

// round 4
// speedup vs baseline: 1.9000x; 1.0363x over previous
#include <cuda_runtime.h>
#include <cuda_bf16.h>
#include <math.h>

// ---------------------------------------------------------------------------
// ComplexRecurrentModel on GB300 (sm_103 non-'a' PTX target).
// mma.sync.m16n8k16 bf16 split-precision GEMMs, cp.async double-buffered.
// Complex GEMMs as real GEMMs on [re|im] 1024-wide layout.
// x = h + l (bf16 each); C = Ah*Bh + Ah*Bl + Al*Bh, fp32 accum.
// ---------------------------------------------------------------------------

#define Bc 4
#define Sc 128
#define Dc 512
#define Mc 4
#define Kc 32
#define NSTEPS 16
#define EPSF 1e-6f
#define SCALEF 0.044194173824159216f   // 512^-0.5

constexpr int ROWS = Bc * Sc;              // 512
constexpr int E2 = 2 * Dc;                 // 1024
constexpr int NBS = Bc * Sc;               // 512
constexpr int NMBS = Mc * NBS;             // 2048
constexpr size_t WELEMS = (size_t)4 * Mc * E2 * E2;
constexpr size_t WTYPE  = (size_t)Mc * E2 * E2;
constexpr size_t WMOD   = (size_t)E2 * E2;

// ---- device buffers -------------------------------------------------------
__device__ __align__(256) __nv_bfloat16 g_WPH[WELEMS];
__device__ __align__(256) __nv_bfloat16 g_WPL[WELEMS];
__device__ __align__(256) __nv_bfloat16 g_Ch[ROWS * E2], g_Cl[ROWS * E2];
__device__ __align__(256) float         g_Z [Mc * ROWS * E2];
__device__ __align__(256) __nv_bfloat16 g_Zh[Mc * ROWS * E2], g_Zl[Mc * ROWS * E2];
__device__ __align__(256) __nv_bfloat16 g_Qh[Mc * ROWS * E2], g_Ql[Mc * ROWS * E2];
__device__ __align__(256) __nv_bfloat16 g_Kh[Mc * ROWS * E2], g_Kl[Mc * ROWS * E2];
__device__ __align__(256) __nv_bfloat16 g_Vth[16 * E2 * Sc], g_Vtl[16 * E2 * Sc]; // [z][d][s]
__device__ __align__(256) float         g_logits[16 * Sc * Sc];
__device__ __align__(256) __nv_bfloat16 g_ATh[16 * Sc * Sc], g_ATl[16 * Sc * Sc];
__device__ __align__(256) float         g_P [Mc * ROWS * E2];
__device__ __align__(256) float g_sr[ROWS * Dc], g_si[ROWS * Dc];
__device__ __align__(256) float g_acc[ROWS * E2];
__device__ __align__(256) float g_mem[Bc * Kc * E2];
__device__ __align__(256) float g_ptrst[Bc * Kc];
__device__ __align__(256) float g_score[NMBS], g_conf[NMBS], g_halt[NMBS];
__device__ __align__(256) float g_read[Bc * E2];
__device__ __align__(256) float g_gate[Mc * Dc];
__device__ __align__(256) float g_rem[16], g_stsc[16], g_stcf[16], g_coef[16];

// ---------------------------------------------------------------------------
// helpers
// ---------------------------------------------------------------------------
__device__ __forceinline__ unsigned smem_u32(const void* p) {
    unsigned a;
    asm("{ .reg .u64 t; cvta.to.shared.u64 t, %1; cvt.u32.u64 %0, t; }" : "=r"(a) : "l"(p));
    return a;
}
__device__ __forceinline__ void cpasync16(unsigned dst, const void* src) {
    asm volatile("cp.async.cg.shared.global [%0], [%1], 16;" :: "r"(dst), "l"(src) : "memory");
}
__device__ __forceinline__ void cp_commit() {
    asm volatile("cp.async.commit_group;" ::: "memory");
}
template <int N> __device__ __forceinline__ void cp_wait() {
    asm volatile("cp.async.wait_group %0;" :: "n"(N) : "memory");
}
__device__ __forceinline__ void ldmat_x4(unsigned (&r)[4], unsigned addr) {
    asm volatile("ldmatrix.sync.aligned.m8n8.x4.shared.b16 {%0,%1,%2,%3}, [%4];"
                 : "=r"(r[0]), "=r"(r[1]), "=r"(r[2]), "=r"(r[3]) : "r"(addr));
}
__device__ __forceinline__ void mma16816(float (&c)[4], const unsigned* a, const unsigned* b) {
    asm volatile("mma.sync.aligned.m16n8k16.row.col.f32.bf16.bf16.f32 "
                 "{%0,%1,%2,%3}, {%4,%5,%6,%7}, {%8,%9}, {%0,%1,%2,%3};"
                 : "+f"(c[0]), "+f"(c[1]), "+f"(c[2]), "+f"(c[3])
                 : "r"(a[0]), "r"(a[1]), "r"(a[2]), "r"(a[3]), "r"(b[0]), "r"(b[1]));
}
__device__ __forceinline__ unsigned swz128(unsigned off) { return off ^ ((off >> 3) & 0x70); }

// ---------------------------------------------------------------------------
// mma.sync GEMM, 2-stage cp.async pipeline.
// D[z][row][col] = sum_k A[z][row][k] * B[z][col][k]
// MODE 0: fp32 out ; MODE 1: split-bf16 out ; MODE 2: split-bf16 transposed V
// MODE 3: fp32 atomicAdd (split-K). KSPLIT: blockIdx.y = K-slice index.
// ---------------------------------------------------------------------------
constexpr int STAGE_BYTES = 65536;                 // Ah,Al,Bh,Bl x 16KB
constexpr int GEMM_SMEM = 2 * STAGE_BYTES;         // 128KB

template <int MODE, bool KSPLIT>
__global__ void __launch_bounds__(256, 1) gemm_mma(
    const __nv_bfloat16* __restrict__ Ah, const __nv_bfloat16* __restrict__ Al,
    int aK, size_t aZ,
    const __nv_bfloat16* __restrict__ Bh, const __nv_bfloat16* __restrict__ Bl,
    int bK, size_t bZ,
    float* __restrict__ outF, __nv_bfloat16* __restrict__ outH, __nv_bfloat16* __restrict__ outL,
    int ldOut, size_t outZ, int ktot)
{
    extern __shared__ char smem_raw[];
    const unsigned sbase = smem_u32(smem_raw);

    const int tid = threadIdx.x;
    const int wid = tid >> 5, lane = tid & 31;
    const int z = blockIdx.z;
    const int col0 = blockIdx.x * 128;
    const int row0 = KSPLIT ? 0 : blockIdx.y * 128;
    const int kbase = KSPLIT ? blockIdx.y * ktot : 0;

    const int warpM = (wid & 3) * 32, warpN = (wid >> 2) * 64;

    const __nv_bfloat16* aP[2] = { Ah + (size_t)z * aZ + (size_t)row0 * aK + kbase,
                                   Al + (size_t)z * aZ + (size_t)row0 * aK + kbase };
    const __nv_bfloat16* bP[2] = { Bh + (size_t)z * bZ + (size_t)col0 * bK + kbase,
                                   Bl + (size_t)z * bZ + (size_t)col0 * bK + kbase };

    float acc[2][8][4];
#pragma unroll
    for (int mt = 0; mt < 2; mt++)
#pragma unroll
        for (int nt = 0; nt < 8; nt++)
#pragma unroll
            for (int q = 0; q < 4; q++) acc[mt][nt][q] = 0.f;

    // per-lane ldmatrix geometry
    const int lmat = lane >> 3, lrow = lane & 7;
    const int a_m = (lmat & 1) * 8 + lrow;
    const int a_k = (lmat >> 1) * 8;
    const int b_n = (lmat >> 1) * 8 + lrow;
    const int b_k = (lmat & 1) * 8;

    // stage loader: 16 cp.async/thread -> [Ah|Al|Bh|Bl] 16KB tiles, SW128
    auto stage_load = [&](int ch, unsigned stg) {
        const int k0 = ch << 6;
#pragma unroll
        for (int hl = 0; hl < 2; hl++) {
            unsigned hOff = hl ? 16384u : 0u;
#pragma unroll
            for (int it = 0; it < 4; it++) {
                int idx = it * 256 + tid;            // 0..1023
                int r = idx >> 3, c = (idx & 7) * 8;
                unsigned so = swz128((unsigned)(r * 128 + c * 2));
                cpasync16(stg + hOff + so, aP[hl] + (size_t)r * aK + k0 + c);
                cpasync16(stg + 32768u + hOff + so, bP[hl] + (size_t)r * bK + k0 + c);
            }
        }
        cp_commit();
    };

    auto compute = [&](unsigned stg) {
        const unsigned sA0 = stg, sA1 = stg + 16384u;
        const unsigned sB0 = stg + 32768u, sB1 = stg + 49152u;
#pragma unroll
        for (int ks = 0; ks < 4; ks++) {
            unsigned ah[2][4], al[2][4];
#pragma unroll
            for (int mt = 0; mt < 2; mt++) {
                int m = warpM + mt * 16 + a_m;
                int kk = ks * 16 + a_k;
                unsigned off = swz128((unsigned)(m * 128 + kk * 2));
                ldmat_x4(ah[mt], sA0 + off);
                ldmat_x4(al[mt], sA1 + off);
            }
            unsigned bh[8][2], bl[8][2];
#pragma unroll
            for (int np = 0; np < 4; np++) {
                int n = warpN + np * 16 + b_n;
                int kk = ks * 16 + b_k;
                unsigned off = swz128((unsigned)(n * 128 + kk * 2));
                unsigned rh[4], rl[4];
                ldmat_x4(rh, sB0 + off);
                ldmat_x4(rl, sB1 + off);
                bh[2 * np][0] = rh[0]; bh[2 * np][1] = rh[1];
                bh[2 * np + 1][0] = rh[2]; bh[2 * np + 1][1] = rh[3];
                bl[2 * np][0] = rl[0]; bl[2 * np][1] = rl[1];
                bl[2 * np + 1][0] = rl[2]; bl[2 * np + 1][1] = rl[3];
            }
#pragma unroll
            for (int mt = 0; mt < 2; mt++)
#pragma unroll
                for (int nt = 0; nt < 8; nt++) {
                    mma16816(acc[mt][nt], ah[mt], bh[nt]);
                    mma16816(acc[mt][nt], ah[mt], bl[nt]);
                    mma16816(acc[mt][nt], al[mt], bh[nt]);
                }
        }
    };

    const int nchunk = ktot >> 6;
    const unsigned stg0 = sbase, stg1 = sbase + (unsigned)STAGE_BYTES;

    stage_load(0, stg0);
    for (int ch = 0; ch < nchunk; ch++) {
        unsigned cur = (ch & 1) ? stg1 : stg0;
        if (ch + 1 < nchunk) {
            stage_load(ch + 1, (ch & 1) ? stg0 : stg1);
            cp_wait<1>();
        } else {
            cp_wait<0>();
        }
        __syncthreads();
        compute(cur);
        __syncthreads();
    }

    // epilogue
    const int erow = lane >> 2, ecol = (lane & 3) * 2;
#pragma unroll
    for (int mt = 0; mt < 2; mt++) {
#pragma unroll
        for (int nt = 0; nt < 8; nt++) {
            const float* c = acc[mt][nt];
#pragma unroll
            for (int half = 0; half < 2; half++) {
                int rowG = row0 + warpM + mt * 16 + erow + half * 8;
                int colG = col0 + warpN + nt * 8 + ecol;
                float v0 = c[half * 2 + 0], v1 = c[half * 2 + 1];
                if (MODE == 0) {
                    float* o = outF + (size_t)z * outZ + (size_t)rowG * ldOut + colG;
                    o[0] = v0; o[1] = v1;
                } else if (MODE == 3) {
                    float* o = outF + (size_t)z * outZ + (size_t)rowG * ldOut + colG;
                    atomicAdd(o + 0, v0);
                    atomicAdd(o + 1, v1);
                } else if (MODE == 1) {
                    size_t base = (size_t)z * outZ + (size_t)rowG * ldOut + colG;
                    __nv_bfloat16 h0 = __float2bfloat16(v0);
                    __nv_bfloat16 h1 = __float2bfloat16(v1);
                    outH[base + 0] = h0; outL[base + 0] = __float2bfloat16(v0 - __bfloat162float(h0));
                    outH[base + 1] = h1; outL[base + 1] = __float2bfloat16(v1 - __bfloat162float(h1));
                } else {
                    const int b = rowG >> 7, s = rowG & 127;
                    __nv_bfloat16 h0 = __float2bfloat16(v0);
                    __nv_bfloat16 h1 = __float2bfloat16(v1);
                    size_t o0 = ((size_t)(z * 4 + b) * E2 + colG) * Sc + s;
                    outH[o0] = h0; outL[o0] = __float2bfloat16(v0 - __bfloat162float(h0));
                    size_t o1 = o0 + Sc;
                    outH[o1] = h1; outL[o1] = __float2bfloat16(v1 - __bfloat162float(h1));
                }
            }
        }
    }
}

// ---------------------------------------------------------------------------
// reductions
// ---------------------------------------------------------------------------
__device__ __forceinline__ float sigm(float x) { return 1.f / (1.f + expf(-x)); }

__device__ __forceinline__ float blockSum128(float v) {
    __shared__ float sh[4];
    int lane = threadIdx.x & 31, w = threadIdx.x >> 5;
#pragma unroll
    for (int o = 16; o; o >>= 1) v += __shfl_xor_sync(0xffffffffu, v, o);
    if (lane == 0) sh[w] = v;
    __syncthreads();
    float r = sh[0] + sh[1] + sh[2] + sh[3];
    __syncthreads();
    return r;
}
__device__ __forceinline__ float blockMax128(float v) {
    __shared__ float sh[4];
    int lane = threadIdx.x & 31, w = threadIdx.x >> 5;
#pragma unroll
    for (int o = 16; o; o >>= 1) v = fmaxf(v, __shfl_xor_sync(0xffffffffu, v, o));
    if (lane == 0) sh[w] = v;
    __syncthreads();
    float r = fmaxf(fmaxf(sh[0], sh[1]), fmaxf(sh[2], sh[3]));
    __syncthreads();
    return r;
}
__device__ __forceinline__ float blockSum256(float v, float* sh) {
    int lane = threadIdx.x & 31, w = threadIdx.x >> 5;
#pragma unroll
    for (int o = 16; o; o >>= 1) v += __shfl_xor_sync(0xffffffffu, v, o);
    if (lane == 0) sh[w] = v;
    __syncthreads();
    float r = 0.f;
#pragma unroll
    for (int i = 0; i < 8; i++) r += sh[i];
    __syncthreads();
    return r;
}

// ---------------------------------------------------------------------------
// elementwise / small kernels
// ---------------------------------------------------------------------------
__global__ void k_pack(const float* __restrict__ Wl_r, const float* __restrict__ Wl_i,
                       const float* __restrict__ Wq_r, const float* __restrict__ Wq_i,
                       const float* __restrict__ Wk_r, const float* __restrict__ Wk_i,
                       const float* __restrict__ Wv_r, const float* __restrict__ Wv_i) {
    size_t idx = (size_t)blockIdx.x * 256 + threadIdx.x;  // 16,777,216
    int k = (int)(idx & 1023), j = (int)((idx >> 10) & 1023);
    int m = (int)((idx >> 20) & 3), t = (int)(idx >> 22);
    const float* Wr; const float* Wi;
    if (t == 0) { Wr = Wl_r; Wi = Wl_i; }
    else if (t == 1) { Wr = Wq_r; Wi = Wq_i; }
    else if (t == 2) { Wr = Wk_r; Wi = Wk_i; }
    else { Wr = Wv_r; Wi = Wv_i; }
    int jj = j & 511, kk = k & 511;
    size_t base = (size_t)m * Dc * Dc + (size_t)jj * Dc + kk;
    float v;
    if (j < Dc) v = (k < Dc) ? Wr[base] : -Wi[base];
    else        v = (k < Dc) ?  Wi[base] :  Wr[base];
    __nv_bfloat16 h = __float2bfloat16(v);
    g_WPH[idx] = h;
    g_WPL[idx] = __float2bfloat16(v - __bfloat162float(h));
}

// init: state, mem, ptr, gate, rem; step-0 C = x (since s0 = x); zero logits
__global__ void k_init(const float* __restrict__ xr, const float* __restrict__ xi,
                       const float* __restrict__ gate_mask) {
    int i = blockIdx.x * 256 + threadIdx.x;   // 524288
    if (i < ROWS * Dc) { g_sr[i] = xr[i]; g_si[i] = xi[i]; }
    if (i < ROWS * E2) {
        g_acc[i] = 0.f;
        int bs = i >> 10, e = i & 1023;
        float v = (e < Dc) ? xr[bs * Dc + e] : xi[bs * Dc + (e - Dc)];
        __nv_bfloat16 h = __float2bfloat16(v);
        g_Ch[i] = h;
        g_Cl[i] = __float2bfloat16(v - __bfloat162float(h));
    }
    if (i < 16 * Sc * Sc) g_logits[i] = 0.f;
    if (i < Bc * Kc * E2) g_mem[i] = 0.f;
    if (i < Bc * Kc) g_ptrst[i] = (i % Kc == 0) ? 1.f : 0.f;
    if (i < Mc * Dc) g_gate[i] = sigm(gate_mask[i]);
    if (i < Bc) g_rem[i] = 1.f;
}

// magnitude LN + phase + modReLU on Z; writes split bf16
__global__ void k_norm(const float* __restrict__ ln_scale,
                       const float* __restrict__ ln_shift,
                       const float* __restrict__ mod_bias) {
    const int row = blockIdx.x;            // m*512 + bs
    const int m = row >> 9;
    const float* zp = g_Z + (size_t)row * E2;
    const int t = threadIdx.x;             // 128 thr, 4 complex each
    float vr[4], vi[4], mg[4];
    float s = 0.f, ss = 0.f;
#pragma unroll
    for (int q = 0; q < 4; q++) {
        int d = t * 4 + q;
        vr[q] = zp[d]; vi[q] = zp[Dc + d];
        mg[q] = sqrtf(vr[q] * vr[q] + vi[q] * vi[q]) + EPSF;
        s += mg[q]; ss += mg[q] * mg[q];
    }
    float sum = blockSum128(s);
    float sumsq = blockSum128(ss);
    float mean = sum * (1.f / Dc);
    float var = (sumsq - (float)Dc * mean * mean) * (1.f / (Dc - 1));
    float rstd = rsqrtf(var + EPSF);
    __nv_bfloat16* oh = g_Zh + (size_t)row * E2;
    __nv_bfloat16* ol = g_Zl + (size_t)row * E2;
#pragma unroll
    for (int q = 0; q < 4; q++) {
        int d = t * 4 + q;
        float nm = (mg[q] - mean) * rstd * ln_scale[m * Dc + d] + ln_shift[m * Dc + d];
        float hyp = sqrtf(vr[q] * vr[q] + vi[q] * vi[q]);
        float c, sn;
        if (hyp > 0.f) { float ih = 1.f / hyp; c = vr[q] * ih; sn = vi[q] * ih; }
        else { c = 1.f; sn = 0.f; }
        float zr2 = nm * c, zi2 = nm * sn;
        float nrm = fabsf(nm) + EPSF;
        float sc = fmaxf(nrm + mod_bias[m * Dc + d], 0.f) / nrm;
        float fr = zr2 * sc, fi = zi2 * sc;
        __nv_bfloat16 hr = __float2bfloat16(fr);
        __nv_bfloat16 hi = __float2bfloat16(fi);
        oh[d] = hr;       ol[d] = __float2bfloat16(fr - __bfloat162float(hr));
        oh[Dc + d] = hi;  ol[Dc + d] = __float2bfloat16(fi - __bfloat162float(hi));
    }
}

// softmax over t of logits*SCALE; writes attn split bf16
__global__ void k_softmax() {
    const int row = blockIdx.x;            // 16*128
    const float* p = g_logits + (size_t)row * Sc;
    float v = p[threadIdx.x] * SCALEF;
    float mx = blockMax128(v);
    float e = expf(v - mx);
    float su = blockSum128(e);
    float a = e / su;
    __nv_bfloat16 h = __float2bfloat16(a);
    g_ATh[(size_t)row * Sc + threadIdx.x] = h;
    g_ATl[(size_t)row * Sc + threadIdx.x] = __float2bfloat16(a - __bfloat162float(h));
}

// gate + score/conf/halt dots; P gated in place
__global__ void k_gatescore(const float* __restrict__ score_w, const float* __restrict__ score_b,
                            const float* __restrict__ conf_w,  const float* __restrict__ conf_b,
                            const float* __restrict__ halt_w,  const float* __restrict__ halt_b) {
    const int row = blockIdx.x;            // m*512 + bs
    const int m = row >> 9;
    float* pp = g_P + (size_t)row * E2;
    const int t = threadIdx.x;
    float sA = 0.f, cA = 0.f, hA = 0.f;
    float rr[4], ii[4];
#pragma unroll
    for (int q = 0; q < 4; q++) {
        int d = t * 4 + q;
        float g = g_gate[m * Dc + d];
        rr[q] = pp[d] * g;
        ii[q] = pp[Dc + d] * g;
        sA += rr[q] * score_w[m * E2 + d] + ii[q] * score_w[m * E2 + Dc + d];
        cA += rr[q] * conf_w[m * E2 + d]  + ii[q] * conf_w[m * E2 + Dc + d];
        hA += rr[q] * halt_w[m * E2 + d]  + ii[q] * halt_w[m * E2 + Dc + d];
    }
#pragma unroll
    for (int q = 0; q < 4; q++) {
        int d = t * 4 + q;
        pp[d] = rr[q]; pp[Dc + d] = ii[q];
    }
    sA = blockSum128(sA); cA = blockSum128(cA); hA = blockSum128(hA);
    if (t == 0) {
        g_score[row] = sA + score_b[m];
        g_conf[row]  = sigm(cA + conf_b[m]);
        g_halt[row]  = sigm(hA + halt_b[m]);
    }
}

// fused stack pipeline: flat-mean, ctrl softmax, ptr update, mem update+read,
// st score/conf, halt mean, rem/coef update. One block per batch, 256 thr.
__global__ void k_stack(const float* __restrict__ cw,  const float* __restrict__ cb,
                        const float* __restrict__ stw, const float* __restrict__ stb,
                        const float* __restrict__ scw, const float* __restrict__ scb) {
    __shared__ float s_flat[E2];
    __shared__ float s_red[8];
    __shared__ float s_ptr[Kc], s_wmask[Kc];
    const int b = blockIdx.x, t = threadIdx.x;

    // flat_in = mean over S of state
    for (int e = t; e < E2; e += 256) {
        const float* base = (e < Dc) ? (g_sr + (size_t)b * Sc * Dc + e)
                                     : (g_si + (size_t)b * Sc * Dc + (e - Dc));
        float s = 0.f;
#pragma unroll 4
        for (int ss = 0; ss < Sc; ss++) s += base[(size_t)ss * Dc];
        s_flat[e] = s * (1.f / Sc);
    }
    __syncthreads();

    // control logits
    float a0 = 0.f, a1 = 0.f, a2 = 0.f;
    for (int e = t; e < E2; e += 256) {
        float fv = s_flat[e];
        a0 += fv * cw[e * 3 + 0];
        a1 += fv * cw[e * 3 + 1];
        a2 += fv * cw[e * 3 + 2];
    }
    a0 = blockSum256(a0, s_red); a1 = blockSum256(a1, s_red); a2 = blockSum256(a2, s_red);
    a0 += cb[0]; a1 += cb[1]; a2 += cb[2];
    float mx3 = fmaxf(a0, fmaxf(a1, a2));
    float e0 = expf(a0 - mx3), e1 = expf(a1 - mx3), e2 = expf(a2 - mx3);
    float is3 = 1.f / (e0 + e1 + e2);
    float push = e0 * is3, pop = e1 * is3, noop = e2 * is3;

    if (t < Kc) {
        float* P = g_ptrst + b * Kc;
        float pu = P[(t + Kc - 1) % Kc];
        float pd = P[(t + 1) % Kc];
        float pc = P[t];
        float np = push * pu + pop * pd + noop * pc;
        float s = np;
#pragma unroll
        for (int o = 16; o; o >>= 1) s += __shfl_xor_sync(0xffffffffu, s, o);
        np /= (s + EPSF);
        P[t] = np;
        s_ptr[t] = np;
        s_wmask[t] = push * pu;
    }
    __syncthreads();

    // mem update + read + st dots
    float s1 = 0.f, s2 = 0.f;
    for (int e = t; e < E2; e += 256) {
        float fv = s_flat[e];
        float racc = 0.f;
#pragma unroll
        for (int k = 0; k < Kc; k++) {
            float w = s_wmask[k];
            size_t mi = ((size_t)(b * Kc + k)) * E2 + e;
            float old = g_mem[mi];
            float nm = fmaf(w, fv - old, old);
            g_mem[mi] = nm;
            racc += nm * s_ptr[k];
        }
        g_read[b * E2 + e] = racc;
        s1 += racc * stw[e];
        s2 += racc * scw[e];
    }
    float h = 0.f;
    for (int idx = t; idx < Mc * Sc; idx += 256)
        h += g_halt[(idx >> 7) * NBS + b * Sc + (idx & 127)];
    s1 = blockSum256(s1, s_red); s2 = blockSum256(s2, s_red); h = blockSum256(h, s_red);
    if (t == 0) {
        g_stsc[b] = s1 + stb[0];
        g_stcf[b] = sigm(s2 + scb[0]);
        float p = h * (1.f / (Mc * Sc));
        float rm = g_rem[b];
        g_coef[b] = p * rm;
        g_rem[b] = rm * (1.f - p);
    }
}

// combine + state write + acc update + NEXT-step C (split bf16) + logits zero
__global__ void k_combine(const float* __restrict__ xr, const float* __restrict__ xi) {
    const int bs = blockIdx.x;
    const int b = bs >> 7;
    float l[5];
#pragma unroll
    for (int m = 0; m < Mc; m++)
        l[m] = g_score[m * NBS + bs] * g_conf[m * NBS + bs];
    l[4] = g_stsc[b] * g_stcf[b];
    float mx = l[0];
#pragma unroll
    for (int m = 1; m < 5; m++) mx = fmaxf(mx, l[m]);
    float w[5], s = 0.f;
#pragma unroll
    for (int m = 0; m < 5; m++) { w[m] = expf(l[m] - mx); s += w[m]; }
    float is = 1.f / s;
#pragma unroll
    for (int m = 0; m < 5; m++) w[m] *= is;
    float cf = g_coef[b];
    const int t = threadIdx.x;
    for (int d = t; d < Dc; d += 128) {
        float nr = w[4] * g_read[b * E2 + d];
        float ni = w[4] * g_read[b * E2 + Dc + d];
#pragma unroll
        for (int m = 0; m < Mc; m++) {
            nr += w[m] * g_P[((size_t)m * NBS + bs) * E2 + d];
            ni += w[m] * g_P[((size_t)m * NBS + bs) * E2 + Dc + d];
        }
        g_sr[(size_t)bs * Dc + d] = nr;
        g_si[(size_t)bs * Dc + d] = ni;
        g_acc[(size_t)bs * E2 + d]      += cf * nr;
        g_acc[(size_t)bs * E2 + Dc + d] += cf * ni;
        // next-step C = 0.5*(x + s_new), split bf16
        float crv = 0.5f * (xr[bs * Dc + d] + nr);
        float civ = 0.5f * (xi[bs * Dc + d] + ni);
        __nv_bfloat16 hr = __float2bfloat16(crv);
        __nv_bfloat16 hi = __float2bfloat16(civ);
        g_Ch[(size_t)bs * E2 + d] = hr;
        g_Cl[(size_t)bs * E2 + d] = __float2bfloat16(crv - __bfloat162float(hr));
        g_Ch[(size_t)bs * E2 + Dc + d] = hi;
        g_Cl[(size_t)bs * E2 + Dc + d] = __float2bfloat16(civ - __bfloat162float(hi));
    }
    // zero logits for next step's split-K atomics (512 blocks x 512 elems)
    for (int i = bs * 512 + t; i < bs * 512 + 512; i += 128) g_logits[i] = 0.f;
}

__global__ void k_final(float* __restrict__ out) {
    int i = blockIdx.x * 256 + threadIdx.x;   // 524288
    int bs = i >> 10, e = i & 1023;
    int b = bs >> 7;
    float st = (e < Dc) ? g_sr[(size_t)bs * Dc + e]
                        : g_si[(size_t)bs * Dc + (e - Dc)];
    out[i] = g_acc[i] + g_rem[b] * st;
}

// ---------------------------------------------------------------------------
extern "C" void kernel_launch(void* const* d_in, const int* in_sizes, int n_in,
                              void* d_out, int out_size) {
    const float* xr        = (const float*)d_in[0];
    const float* xi        = (const float*)d_in[1];
    const float* Wl_r      = (const float*)d_in[2];
    const float* Wl_i      = (const float*)d_in[3];
    const float* Wq_r      = (const float*)d_in[4];
    const float* Wq_i      = (const float*)d_in[5];
    const float* Wk_r      = (const float*)d_in[6];
    const float* Wk_i      = (const float*)d_in[7];
    const float* Wv_r      = (const float*)d_in[8];
    const float* Wv_i      = (const float*)d_in[9];
    const float* ln_scale  = (const float*)d_in[10];
    const float* ln_shift  = (const float*)d_in[11];
    const float* mod_bias  = (const float*)d_in[12];
    const float* gate_mask = (const float*)d_in[13];
    const float* score_w   = (const float*)d_in[14];
    const float* score_b   = (const float*)d_in[15];
    const float* conf_w    = (const float*)d_in[16];
    const float* conf_b    = (const float*)d_in[17];
    const float* halt_w    = (const float*)d_in[18];
    const float* halt_b    = (const float*)d_in[19];
    const float* ctrl_w    = (const float*)d_in[20];
    const float* ctrl_b    = (const float*)d_in[21];
    const float* st_score_w= (const float*)d_in[22];
    const float* st_score_b= (const float*)d_in[23];
    const float* st_conf_w = (const float*)d_in[24];
    const float* st_conf_b = (const float*)d_in[25];

    cudaFuncSetAttribute(gemm_mma<0,false>, cudaFuncAttributeMaxDynamicSharedMemorySize, GEMM_SMEM);
    cudaFuncSetAttribute(gemm_mma<1,false>, cudaFuncAttributeMaxDynamicSharedMemorySize, GEMM_SMEM);
    cudaFuncSetAttribute(gemm_mma<2,false>, cudaFuncAttributeMaxDynamicSharedMemorySize, GEMM_SMEM);
    cudaFuncSetAttribute(gemm_mma<3,true>,  cudaFuncAttributeMaxDynamicSharedMemorySize, GEMM_SMEM);
    cudaFuncSetAttribute(gemm_mma<0,false>, cudaFuncAttributePreferredSharedMemoryCarveout, 100);

    __nv_bfloat16 *WPH, *WPL, *Ch, *Cl, *Zh, *Zl, *Qh, *Ql, *Kh, *Kl, *Vth, *Vtl, *ATh, *ATl;
    float *Z, *LG, *P;
    cudaGetSymbolAddress((void**)&WPH, g_WPH);
    cudaGetSymbolAddress((void**)&WPL, g_WPL);
    cudaGetSymbolAddress((void**)&Ch, g_Ch);
    cudaGetSymbolAddress((void**)&Cl, g_Cl);
    cudaGetSymbolAddress((void**)&Z, g_Z);
    cudaGetSymbolAddress((void**)&Zh, g_Zh);
    cudaGetSymbolAddress((void**)&Zl, g_Zl);
    cudaGetSymbolAddress((void**)&Qh, g_Qh);
    cudaGetSymbolAddress((void**)&Ql, g_Ql);
    cudaGetSymbolAddress((void**)&Kh, g_Kh);
    cudaGetSymbolAddress((void**)&Kl, g_Kl);
    cudaGetSymbolAddress((void**)&Vth, g_Vth);
    cudaGetSymbolAddress((void**)&Vtl, g_Vtl);
    cudaGetSymbolAddress((void**)&LG, g_logits);
    cudaGetSymbolAddress((void**)&ATh, g_ATh);
    cudaGetSymbolAddress((void**)&ATl, g_ATl);
    cudaGetSymbolAddress((void**)&P, g_P);

    k_pack<<<65536, 256>>>(Wl_r, Wl_i, Wq_r, Wq_i, Wk_r, Wk_i, Wv_r, Wv_i);
    k_init<<<2048, 256>>>(xr, xi, gate_mask);

    for (int step = 0; step < NSTEPS; step++) {
        // Z = C x WlP  (A shared over modules)
        gemm_mma<0,false><<<dim3(8, 4, Mc), 256, GEMM_SMEM>>>(
            Ch, Cl, E2, 0,
            WPH + 0 * WTYPE, WPL + 0 * WTYPE, E2, WMOD,
            Z, nullptr, nullptr, E2, (size_t)ROWS * E2, E2);
        k_norm<<<NMBS, 128>>>(ln_scale, ln_shift, mod_bias);
        // Q, K (split-bf16 out), V (transposed split-bf16 out)
        gemm_mma<1,false><<<dim3(8, 4, Mc), 256, GEMM_SMEM>>>(
            Zh, Zl, E2, (size_t)ROWS * E2,
            WPH + 1 * WTYPE, WPL + 1 * WTYPE, E2, WMOD,
            nullptr, Qh, Ql, E2, (size_t)ROWS * E2, E2);
        gemm_mma<1,false><<<dim3(8, 4, Mc), 256, GEMM_SMEM>>>(
            Zh, Zl, E2, (size_t)ROWS * E2,
            WPH + 2 * WTYPE, WPL + 2 * WTYPE, E2, WMOD,
            nullptr, Kh, Kl, E2, (size_t)ROWS * E2, E2);
        gemm_mma<2,false><<<dim3(8, 4, Mc), 256, GEMM_SMEM>>>(
            Zh, Zl, E2, (size_t)ROWS * E2,
            WPH + 3 * WTYPE, WPL + 3 * WTYPE, E2, WMOD,
            nullptr, Vth, Vtl, 0, 0, E2);
        // logits = Q.K^T (split-K=4, atomic accumulate into zeroed buffer)
        gemm_mma<3,true><<<dim3(1, 4, 16), 256, GEMM_SMEM>>>(
            Qh, Ql, E2, (size_t)Sc * E2,
            Kh, Kl, E2, (size_t)Sc * E2,
            LG, nullptr, nullptr, Sc, (size_t)Sc * Sc, 256);
        k_softmax<<<16 * Sc, 128>>>();
        // P = attn . Vt^T   (K = 128)
        gemm_mma<0,false><<<dim3(8, 1, 16), 256, GEMM_SMEM>>>(
            ATh, ATl, Sc, (size_t)Sc * Sc,
            Vth, Vtl, Sc, (size_t)E2 * Sc,
            P, nullptr, nullptr, E2, (size_t)Sc * E2, Sc);
        k_gatescore<<<NMBS, 128>>>(score_w, score_b, conf_w, conf_b, halt_w, halt_b);
        k_stack<<<Bc, 256>>>(ctrl_w, ctrl_b, st_score_w, st_score_b, st_conf_w, st_conf_b);
        k_combine<<<NBS, 128>>>(xr, xi);
    }
    k_final<<<2048, 256>>>((float*)d_out);
}

// round 5
// speedup vs baseline: 2.8253x; 1.4870x over previous
#include <cuda_runtime.h>
#include <cuda_bf16.h>
#include <math.h>

// ---------------------------------------------------------------------------
// ComplexRecurrentModel on GB300 (sm_103 non-'a' PTX target).
// mma.sync.m16n8k16 bf16 split-precision GEMMs, 3-stage cp.async pipeline.
// Fused QKV projection GEMM. Vectorized elementwise kernels.
// x = h + l (bf16 each); C = Ah*Bh + Ah*Bl + Al*Bh, fp32 accum.
// ---------------------------------------------------------------------------

#define Bc 4
#define Sc 128
#define Dc 512
#define Mc 4
#define Kc 32
#define NSTEPS 16
#define EPSF 1e-6f
#define SCALEF 0.044194173824159216f   // 512^-0.5

constexpr int ROWS = Bc * Sc;              // 512
constexpr int E2 = 2 * Dc;                 // 1024
constexpr int NBS = Bc * Sc;               // 512
constexpr int NMBS = Mc * NBS;             // 2048
constexpr size_t WELEMS = (size_t)4 * Mc * E2 * E2;
constexpr size_t WTYPE  = (size_t)Mc * E2 * E2;
constexpr size_t WMOD   = (size_t)E2 * E2;

// ---- device buffers -------------------------------------------------------
__device__ __align__(256) __nv_bfloat16 g_WPH[WELEMS];
__device__ __align__(256) __nv_bfloat16 g_WPL[WELEMS];
__device__ __align__(256) __nv_bfloat16 g_Ch[ROWS * E2], g_Cl[ROWS * E2];
__device__ __align__(256) float         g_Z [Mc * ROWS * E2];
__device__ __align__(256) __nv_bfloat16 g_Zh[Mc * ROWS * E2], g_Zl[Mc * ROWS * E2];
__device__ __align__(256) __nv_bfloat16 g_Qh[Mc * ROWS * E2], g_Ql[Mc * ROWS * E2];
__device__ __align__(256) __nv_bfloat16 g_Kh[Mc * ROWS * E2], g_Kl[Mc * ROWS * E2];
__device__ __align__(256) __nv_bfloat16 g_Vth[16 * E2 * Sc], g_Vtl[16 * E2 * Sc]; // [z][d][s]
__device__ __align__(256) float         g_logits[16 * Sc * Sc];
__device__ __align__(256) __nv_bfloat16 g_ATh[16 * Sc * Sc], g_ATl[16 * Sc * Sc];
__device__ __align__(256) float         g_P [Mc * ROWS * E2];
__device__ __align__(256) float g_sr[ROWS * Dc], g_si[ROWS * Dc];
__device__ __align__(256) float g_acc[ROWS * E2];
__device__ __align__(256) float g_mem[Bc * Kc * E2];
__device__ __align__(256) float g_ptrst[Bc * Kc];
__device__ __align__(256) float g_score[NMBS], g_conf[NMBS], g_halt[NMBS];
__device__ __align__(256) float g_flat[Bc * E2], g_read[Bc * E2];
__device__ __align__(256) float g_gate[Mc * Dc];
__device__ __align__(256) float g_rem[16], g_stsc[16], g_stcf[16], g_coef[16];

// ---------------------------------------------------------------------------
// helpers
// ---------------------------------------------------------------------------
__device__ __forceinline__ unsigned smem_u32(const void* p) {
    unsigned a;
    asm("{ .reg .u64 t; cvta.to.shared.u64 t, %1; cvt.u32.u64 %0, t; }" : "=r"(a) : "l"(p));
    return a;
}
__device__ __forceinline__ void cpasync16(unsigned dst, const void* src) {
    asm volatile("cp.async.cg.shared.global [%0], [%1], 16;" :: "r"(dst), "l"(src) : "memory");
}
__device__ __forceinline__ void cp_commit() {
    asm volatile("cp.async.commit_group;" ::: "memory");
}
template <int N> __device__ __forceinline__ void cp_wait() {
    asm volatile("cp.async.wait_group %0;" :: "n"(N) : "memory");
}
__device__ __forceinline__ void ldmat_x4(unsigned (&r)[4], unsigned addr) {
    asm volatile("ldmatrix.sync.aligned.m8n8.x4.shared.b16 {%0,%1,%2,%3}, [%4];"
                 : "=r"(r[0]), "=r"(r[1]), "=r"(r[2]), "=r"(r[3]) : "r"(addr));
}
__device__ __forceinline__ void mma16816(float (&c)[4], const unsigned* a, const unsigned* b) {
    asm volatile("mma.sync.aligned.m16n8k16.row.col.f32.bf16.bf16.f32 "
                 "{%0,%1,%2,%3}, {%4,%5,%6,%7}, {%8,%9}, {%0,%1,%2,%3};"
                 : "+f"(c[0]), "+f"(c[1]), "+f"(c[2]), "+f"(c[3])
                 : "r"(a[0]), "r"(a[1]), "r"(a[2]), "r"(a[3]), "r"(b[0]), "r"(b[1]));
}
__device__ __forceinline__ unsigned swz128(unsigned off) { return off ^ ((off >> 3) & 0x70); }
__device__ __forceinline__ unsigned pkbf2(float a, float b) {
    __nv_bfloat162 t = __floats2bfloat162_rn(a, b);
    return *(unsigned*)&t;
}
__device__ __forceinline__ float bflo(float v) {   // v - bf16(v)
    __nv_bfloat16 h = __float2bfloat16(v);
    return v - __bfloat162float(h);
}

constexpr int STAGE_BYTES = 65536;                 // Ah,Al,Bh,Bl x 16KB
constexpr int GEMM_SMEM = 3 * STAGE_BYTES;         // 192KB, 3-stage

// ---------------------------------------------------------------------------
// shared mainloop pieces (macro-ish inline functions on raw addresses)
// ---------------------------------------------------------------------------
struct MmaCtx {
    unsigned sbase;
    int warpM, warpN;
    int a_m, a_k, b_n, b_k;
};

__device__ __forceinline__ void mma_compute(const MmaCtx& cx, unsigned stg, float acc[2][8][4]) {
    const unsigned sA0 = stg, sA1 = stg + 16384u;
    const unsigned sB0 = stg + 32768u, sB1 = stg + 49152u;
#pragma unroll
    for (int ks = 0; ks < 4; ks++) {
        unsigned ah[2][4], al[2][4];
#pragma unroll
        for (int mt = 0; mt < 2; mt++) {
            int m = cx.warpM + mt * 16 + cx.a_m;
            int kk = ks * 16 + cx.a_k;
            unsigned off = swz128((unsigned)(m * 128 + kk * 2));
            ldmat_x4(ah[mt], sA0 + off);
            ldmat_x4(al[mt], sA1 + off);
        }
        unsigned bh[8][2], bl[8][2];
#pragma unroll
        for (int np = 0; np < 4; np++) {
            int n = cx.warpN + np * 16 + cx.b_n;
            int kk = ks * 16 + cx.b_k;
            unsigned off = swz128((unsigned)(n * 128 + kk * 2));
            unsigned rh[4], rl[4];
            ldmat_x4(rh, sB0 + off);
            ldmat_x4(rl, sB1 + off);
            bh[2 * np][0] = rh[0]; bh[2 * np][1] = rh[1];
            bh[2 * np + 1][0] = rh[2]; bh[2 * np + 1][1] = rh[3];
            bl[2 * np][0] = rl[0]; bl[2 * np][1] = rl[1];
            bl[2 * np + 1][0] = rl[2]; bl[2 * np + 1][1] = rl[3];
        }
#pragma unroll
        for (int mt = 0; mt < 2; mt++)
#pragma unroll
            for (int nt = 0; nt < 8; nt++) {
                mma16816(acc[mt][nt], ah[mt], bh[nt]);
                mma16816(acc[mt][nt], ah[mt], bl[nt]);
                mma16816(acc[mt][nt], al[mt], bh[nt]);
            }
    }
}

__device__ __forceinline__ void mma_stage_load(
    int tid, unsigned stg, int k0,
    const __nv_bfloat16* aPh, const __nv_bfloat16* aPl, int aK,
    const __nv_bfloat16* bPh, const __nv_bfloat16* bPl, int bK) {
    const __nv_bfloat16* aa[2] = { aPh, aPl };
    const __nv_bfloat16* bb[2] = { bPh, bPl };
#pragma unroll
    for (int hl = 0; hl < 2; hl++) {
        unsigned hOff = hl ? 16384u : 0u;
#pragma unroll
        for (int it = 0; it < 4; it++) {
            int idx = it * 256 + tid;            // 0..1023
            int r = idx >> 3, c = (idx & 7) * 8;
            unsigned so = swz128((unsigned)(r * 128 + c * 2));
            cpasync16(stg + hOff + so, aa[hl] + (size_t)r * aK + k0 + c);
            cpasync16(stg + 32768u + hOff + so, bb[hl] + (size_t)r * bK + k0 + c);
        }
    }
    cp_commit();
}

// ---------------------------------------------------------------------------
// generic GEMM: MODE 0 fp32 out ; MODE 3 fp32 atomicAdd (split-K)
// ---------------------------------------------------------------------------
template <int MODE, bool KSPLIT>
__global__ void __launch_bounds__(256, 1) gemm_mma(
    const __nv_bfloat16* __restrict__ Ah, const __nv_bfloat16* __restrict__ Al,
    int aK, size_t aZ,
    const __nv_bfloat16* __restrict__ Bh, const __nv_bfloat16* __restrict__ Bl,
    int bK, size_t bZ,
    float* __restrict__ outF, int ldOut, size_t outZ, int ktot)
{
    extern __shared__ char smem_raw[];
    const unsigned sbase = smem_u32(smem_raw);
    const int tid = threadIdx.x;
    const int wid = tid >> 5, lane = tid & 31;
    const int z = blockIdx.z;
    const int col0 = blockIdx.x * 128;
    const int row0 = KSPLIT ? 0 : blockIdx.y * 128;
    const int kbase = KSPLIT ? blockIdx.y * ktot : 0;

    MmaCtx cx;
    cx.sbase = sbase;
    cx.warpM = (wid & 3) * 32; cx.warpN = (wid >> 2) * 64;
    const int lmat = lane >> 3, lrow = lane & 7;
    cx.a_m = (lmat & 1) * 8 + lrow; cx.a_k = (lmat >> 1) * 8;
    cx.b_n = (lmat >> 1) * 8 + lrow; cx.b_k = (lmat & 1) * 8;

    const __nv_bfloat16* aPh = Ah + (size_t)z * aZ + (size_t)row0 * aK + kbase;
    const __nv_bfloat16* aPl = Al + (size_t)z * aZ + (size_t)row0 * aK + kbase;
    const __nv_bfloat16* bPh = Bh + (size_t)z * bZ + (size_t)col0 * bK + kbase;
    const __nv_bfloat16* bPl = Bl + (size_t)z * bZ + (size_t)col0 * bK + kbase;

    float acc[2][8][4];
#pragma unroll
    for (int mt = 0; mt < 2; mt++)
#pragma unroll
        for (int nt = 0; nt < 8; nt++)
#pragma unroll
            for (int q = 0; q < 4; q++) acc[mt][nt][q] = 0.f;

    const int nchunk = ktot >> 6;
    auto stg = [&](int i) { return sbase + (unsigned)((i % 3) * STAGE_BYTES); };

    mma_stage_load(tid, stg(0), 0, aPh, aPl, aK, bPh, bPl, bK);
    if (nchunk > 1) mma_stage_load(tid, stg(1), 64, aPh, aPl, aK, bPh, bPl, bK);
    for (int ch = 0; ch < nchunk; ch++) {
        if (ch + 2 < nchunk) {
            mma_stage_load(tid, stg(ch + 2), (ch + 2) << 6, aPh, aPl, aK, bPh, bPl, bK);
            cp_wait<2>();
        } else if (ch + 1 < nchunk) {
            cp_wait<1>();
        } else {
            cp_wait<0>();
        }
        __syncthreads();
        mma_compute(cx, stg(ch), acc);
        __syncthreads();
    }

    const int erow = lane >> 2, ecol = (lane & 3) * 2;
#pragma unroll
    for (int mt = 0; mt < 2; mt++)
#pragma unroll
        for (int nt = 0; nt < 8; nt++) {
            const float* c = acc[mt][nt];
#pragma unroll
            for (int half = 0; half < 2; half++) {
                int rowG = row0 + cx.warpM + mt * 16 + erow + half * 8;
                int colG = col0 + cx.warpN + nt * 8 + ecol;
                float v0 = c[half * 2 + 0], v1 = c[half * 2 + 1];
                float* o = outF + (size_t)z * outZ + (size_t)rowG * ldOut + colG;
                if (MODE == 0) { o[0] = v0; o[1] = v1; }
                else { atomicAdd(o + 0, v0); atomicAdd(o + 1, v1); }
            }
        }
}

// ---------------------------------------------------------------------------
// fused QKV GEMM. blockIdx.x in [0,24): qtype = x>>3 (0=Q,1=K,2=V),
// col0 = (x&7)*128. A = Z (per-module), B = packed weights type 1+qtype.
// Q,K -> split-bf16 row-major ; V -> split-bf16 transposed [z][d][s].
// ---------------------------------------------------------------------------
__global__ void __launch_bounds__(256, 1) gemm_qkv(
    const __nv_bfloat16* __restrict__ Ah, const __nv_bfloat16* __restrict__ Al,
    const __nv_bfloat16* __restrict__ WH, const __nv_bfloat16* __restrict__ WL,
    __nv_bfloat16* __restrict__ Qh, __nv_bfloat16* __restrict__ Ql,
    __nv_bfloat16* __restrict__ Kh, __nv_bfloat16* __restrict__ Kl,
    __nv_bfloat16* __restrict__ Vth, __nv_bfloat16* __restrict__ Vtl)
{
    extern __shared__ char smem_raw[];
    const unsigned sbase = smem_u32(smem_raw);
    const int tid = threadIdx.x;
    const int wid = tid >> 5, lane = tid & 31;
    const int m = blockIdx.z;
    const int qtype = blockIdx.x >> 3;
    const int col0 = (blockIdx.x & 7) * 128;
    const int row0 = blockIdx.y * 128;

    MmaCtx cx;
    cx.sbase = sbase;
    cx.warpM = (wid & 3) * 32; cx.warpN = (wid >> 2) * 64;
    const int lmat = lane >> 3, lrow = lane & 7;
    cx.a_m = (lmat & 1) * 8 + lrow; cx.a_k = (lmat >> 1) * 8;
    cx.b_n = (lmat >> 1) * 8 + lrow; cx.b_k = (lmat & 1) * 8;

    const __nv_bfloat16* aPh = Ah + (size_t)m * (ROWS * E2) + (size_t)row0 * E2;
    const __nv_bfloat16* aPl = Al + (size_t)m * (ROWS * E2) + (size_t)row0 * E2;
    const __nv_bfloat16* bPh = WH + (size_t)qtype * WTYPE + (size_t)m * WMOD + (size_t)col0 * E2;
    const __nv_bfloat16* bPl = WL + (size_t)qtype * WTYPE + (size_t)m * WMOD + (size_t)col0 * E2;

    float acc[2][8][4];
#pragma unroll
    for (int mt = 0; mt < 2; mt++)
#pragma unroll
        for (int nt = 0; nt < 8; nt++)
#pragma unroll
            for (int q = 0; q < 4; q++) acc[mt][nt][q] = 0.f;

    auto stg = [&](int i) { return sbase + (unsigned)((i % 3) * STAGE_BYTES); };
    const int nchunk = 16;
    mma_stage_load(tid, stg(0), 0, aPh, aPl, E2, bPh, bPl, E2);
    mma_stage_load(tid, stg(1), 64, aPh, aPl, E2, bPh, bPl, E2);
    for (int ch = 0; ch < nchunk; ch++) {
        if (ch + 2 < nchunk) {
            mma_stage_load(tid, stg(ch + 2), (ch + 2) << 6, aPh, aPl, E2, bPh, bPl, E2);
            cp_wait<2>();
        } else if (ch + 1 < nchunk) cp_wait<1>();
        else cp_wait<0>();
        __syncthreads();
        mma_compute(cx, stg(ch), acc);
        __syncthreads();
    }

    __nv_bfloat16* OH = (qtype == 0) ? Qh : Kh;
    __nv_bfloat16* OL = (qtype == 0) ? Ql : Kl;
    const int erow = lane >> 2, ecol = (lane & 3) * 2;
#pragma unroll
    for (int mt = 0; mt < 2; mt++)
#pragma unroll
        for (int nt = 0; nt < 8; nt++) {
            const float* c = acc[mt][nt];
#pragma unroll
            for (int half = 0; half < 2; half++) {
                int rowG = row0 + cx.warpM + mt * 16 + erow + half * 8;
                int colG = col0 + cx.warpN + nt * 8 + ecol;
                float v0 = c[half * 2 + 0], v1 = c[half * 2 + 1];
                if (qtype < 2) {
                    size_t base = (size_t)m * (ROWS * E2) + (size_t)rowG * E2 + colG;
                    *(unsigned*)(OH + base) = pkbf2(v0, v1);
                    *(unsigned*)(OL + base) = pkbf2(bflo(v0), bflo(v1));
                } else {
                    const int b = rowG >> 7, s = rowG & 127;
                    size_t o0 = ((size_t)(m * 4 + b) * E2 + colG) * Sc + s;
                    Vth[o0] = __float2bfloat16(v0);
                    Vtl[o0] = __float2bfloat16(bflo(v0));
                    Vth[o0 + Sc] = __float2bfloat16(v1);
                    Vtl[o0 + Sc] = __float2bfloat16(bflo(v1));
                }
            }
        }
}

// ---------------------------------------------------------------------------
// reductions
// ---------------------------------------------------------------------------
__device__ __forceinline__ float sigm(float x) { return 1.f / (1.f + expf(-x)); }

__device__ __forceinline__ float blockSum128(float v) {
    __shared__ float sh[4];
    int lane = threadIdx.x & 31, w = threadIdx.x >> 5;
#pragma unroll
    for (int o = 16; o; o >>= 1) v += __shfl_xor_sync(0xffffffffu, v, o);
    if (lane == 0) sh[w] = v;
    __syncthreads();
    float r = sh[0] + sh[1] + sh[2] + sh[3];
    __syncthreads();
    return r;
}
__device__ __forceinline__ float blockMax128(float v) {
    __shared__ float sh[4];
    int lane = threadIdx.x & 31, w = threadIdx.x >> 5;
#pragma unroll
    for (int o = 16; o; o >>= 1) v = fmaxf(v, __shfl_xor_sync(0xffffffffu, v, o));
    if (lane == 0) sh[w] = v;
    __syncthreads();
    float r = fmaxf(fmaxf(sh[0], sh[1]), fmaxf(sh[2], sh[3]));
    __syncthreads();
    return r;
}
__device__ __forceinline__ float blockSum256(float v, float* sh) {
    int lane = threadIdx.x & 31, w = threadIdx.x >> 5;
#pragma unroll
    for (int o = 16; o; o >>= 1) v += __shfl_xor_sync(0xffffffffu, v, o);
    if (lane == 0) sh[w] = v;
    __syncthreads();
    float r = 0.f;
#pragma unroll
    for (int i = 0; i < 8; i++) r += sh[i];
    __syncthreads();
    return r;
}

// ---------------------------------------------------------------------------
// elementwise / small kernels
// ---------------------------------------------------------------------------
__global__ void k_pack(const float* __restrict__ Wl_r, const float* __restrict__ Wl_i,
                       const float* __restrict__ Wq_r, const float* __restrict__ Wq_i,
                       const float* __restrict__ Wk_r, const float* __restrict__ Wk_i,
                       const float* __restrict__ Wv_r, const float* __restrict__ Wv_i) {
    size_t idx = (size_t)blockIdx.x * 256 + threadIdx.x;  // 16,777,216
    int k = (int)(idx & 1023), j = (int)((idx >> 10) & 1023);
    int m = (int)((idx >> 20) & 3), t = (int)(idx >> 22);
    const float* Wr; const float* Wi;
    if (t == 0) { Wr = Wl_r; Wi = Wl_i; }
    else if (t == 1) { Wr = Wq_r; Wi = Wq_i; }
    else if (t == 2) { Wr = Wk_r; Wi = Wk_i; }
    else { Wr = Wv_r; Wi = Wv_i; }
    int jj = j & 511, kk = k & 511;
    size_t base = (size_t)m * Dc * Dc + (size_t)jj * Dc + kk;
    float v;
    if (j < Dc) v = (k < Dc) ? Wr[base] : -Wi[base];
    else        v = (k < Dc) ?  Wi[base] :  Wr[base];
    g_WPH[idx] = __float2bfloat16(v);
    g_WPL[idx] = __float2bfloat16(bflo(v));
}

// init: state, mem, ptr, gate, rem, flat (mean of x), step-0 C = x, zero logits
__global__ void k_init(const float* __restrict__ xr, const float* __restrict__ xi,
                       const float* __restrict__ gate_mask) {
    int i = blockIdx.x * 256 + threadIdx.x;   // 524288
    if (i < ROWS * Dc) { g_sr[i] = xr[i]; g_si[i] = xi[i]; }
    if (i < ROWS * E2) {
        g_acc[i] = 0.f;
        int bs = i >> 10, e = i & 1023;
        float v = (e < Dc) ? xr[bs * Dc + e] : xi[bs * Dc + (e - Dc)];
        g_Ch[i] = __float2bfloat16(v);
        g_Cl[i] = __float2bfloat16(bflo(v));
    }
    if (i < 16 * Sc * Sc) g_logits[i] = 0.f;
    if (i < Bc * Kc * E2) g_mem[i] = 0.f;
    if (i < Bc * Kc) g_ptrst[i] = (i % Kc == 0) ? 1.f : 0.f;
    if (i < Mc * Dc) g_gate[i] = sigm(gate_mask[i]);
    if (i < Bc) g_rem[i] = 1.f;
    if (i < Bc * E2) {   // flat_in for step 0 = mean over S of x
        int b = i >> 10, e = i & 1023;
        const float* base = (e < Dc) ? (xr + (size_t)b * Sc * Dc + e)
                                     : (xi + (size_t)b * Sc * Dc + (e - Dc));
        float s = 0.f;
#pragma unroll 4
        for (int ss = 0; ss < Sc; ss++) s += base[(size_t)ss * Dc];
        g_flat[i] = s * (1.f / Sc);
    }
}

// magnitude LN + phase + modReLU on Z; float4 in, packed bf16 out
__global__ void k_norm(const float* __restrict__ ln_scale,
                       const float* __restrict__ ln_shift,
                       const float* __restrict__ mod_bias) {
    const int row = blockIdx.x;            // m*512 + bs
    const int m = row >> 9;
    const float* zp = g_Z + (size_t)row * E2;
    const int t = threadIdx.x;             // 128 thr, 4 complex each
    float4 r4 = *(const float4*)(zp + 4 * t);
    float4 i4 = *(const float4*)(zp + Dc + 4 * t);
    float vr[4] = {r4.x, r4.y, r4.z, r4.w};
    float vi[4] = {i4.x, i4.y, i4.z, i4.w};
    float mg[4];
    float s = 0.f, ss = 0.f;
#pragma unroll
    for (int q = 0; q < 4; q++) {
        mg[q] = sqrtf(vr[q] * vr[q] + vi[q] * vi[q]) + EPSF;
        s += mg[q]; ss += mg[q] * mg[q];
    }
    float sum = blockSum128(s);
    float sumsq = blockSum128(ss);
    float mean = sum * (1.f / Dc);
    float var = (sumsq - (float)Dc * mean * mean) * (1.f / (Dc - 1));
    float rstd = rsqrtf(var + EPSF);
    float4 lsc = *(const float4*)(ln_scale + m * Dc + 4 * t);
    float4 lsh = *(const float4*)(ln_shift + m * Dc + 4 * t);
    float4 mb  = *(const float4*)(mod_bias + m * Dc + 4 * t);
    float lscv[4] = {lsc.x, lsc.y, lsc.z, lsc.w};
    float lshv[4] = {lsh.x, lsh.y, lsh.z, lsh.w};
    float mbv[4]  = {mb.x, mb.y, mb.z, mb.w};
    float fr[4], fi[4];
#pragma unroll
    for (int q = 0; q < 4; q++) {
        float nm = (mg[q] - mean) * rstd * lscv[q] + lshv[q];
        float hyp = sqrtf(vr[q] * vr[q] + vi[q] * vi[q]);
        float c, sn;
        if (hyp > 0.f) { float ih = 1.f / hyp; c = vr[q] * ih; sn = vi[q] * ih; }
        else { c = 1.f; sn = 0.f; }
        float zr2 = nm * c, zi2 = nm * sn;
        float nrm = fabsf(nm) + EPSF;
        float sc = fmaxf(nrm + mbv[q], 0.f) / nrm;
        fr[q] = zr2 * sc; fi[q] = zi2 * sc;
    }
    __nv_bfloat16* oh = g_Zh + (size_t)row * E2;
    __nv_bfloat16* ol = g_Zl + (size_t)row * E2;
    uint2 uh = make_uint2(pkbf2(fr[0], fr[1]), pkbf2(fr[2], fr[3]));
    uint2 ul = make_uint2(pkbf2(bflo(fr[0]), bflo(fr[1])), pkbf2(bflo(fr[2]), bflo(fr[3])));
    *(uint2*)(oh + 4 * t) = uh;
    *(uint2*)(ol + 4 * t) = ul;
    uh = make_uint2(pkbf2(fi[0], fi[1]), pkbf2(fi[2], fi[3]));
    ul = make_uint2(pkbf2(bflo(fi[0]), bflo(fi[1])), pkbf2(bflo(fi[2]), bflo(fi[3])));
    *(uint2*)(oh + Dc + 4 * t) = uh;
    *(uint2*)(ol + Dc + 4 * t) = ul;
}

// softmax over t of logits*SCALE; writes attn split bf16
__global__ void k_softmax() {
    const int row = blockIdx.x;            // 16*128
    const float* p = g_logits + (size_t)row * Sc;
    float v = p[threadIdx.x] * SCALEF;
    float mx = blockMax128(v);
    float e = expf(v - mx);
    float su = blockSum128(e);
    float a = e / su;
    g_ATh[(size_t)row * Sc + threadIdx.x] = __float2bfloat16(a);
    g_ATl[(size_t)row * Sc + threadIdx.x] = __float2bfloat16(bflo(a));
}

// gate + score/conf/halt dots; P gated in place; float4
__global__ void k_gatescore(const float* __restrict__ score_w, const float* __restrict__ score_b,
                            const float* __restrict__ conf_w,  const float* __restrict__ conf_b,
                            const float* __restrict__ halt_w,  const float* __restrict__ halt_b) {
    const int row = blockIdx.x;            // m*512 + bs
    const int m = row >> 9;
    float* pp = g_P + (size_t)row * E2;
    const int t = threadIdx.x;
    float4 pr = *(float4*)(pp + 4 * t);
    float4 pi = *(float4*)(pp + Dc + 4 * t);
    float4 gg = *(const float4*)(g_gate + m * Dc + 4 * t);
    float rr[4] = {pr.x * gg.x, pr.y * gg.y, pr.z * gg.z, pr.w * gg.w};
    float ii[4] = {pi.x * gg.x, pi.y * gg.y, pi.z * gg.z, pi.w * gg.w};
    float4 swr = *(const float4*)(score_w + m * E2 + 4 * t);
    float4 swi = *(const float4*)(score_w + m * E2 + Dc + 4 * t);
    float4 cwr = *(const float4*)(conf_w + m * E2 + 4 * t);
    float4 cwi = *(const float4*)(conf_w + m * E2 + Dc + 4 * t);
    float4 hwr = *(const float4*)(halt_w + m * E2 + 4 * t);
    float4 hwi = *(const float4*)(halt_w + m * E2 + Dc + 4 * t);
    float sA = rr[0]*swr.x + rr[1]*swr.y + rr[2]*swr.z + rr[3]*swr.w
             + ii[0]*swi.x + ii[1]*swi.y + ii[2]*swi.z + ii[3]*swi.w;
    float cA = rr[0]*cwr.x + rr[1]*cwr.y + rr[2]*cwr.z + rr[3]*cwr.w
             + ii[0]*cwi.x + ii[1]*cwi.y + ii[2]*cwi.z + ii[3]*cwi.w;
    float hA = rr[0]*hwr.x + rr[1]*hwr.y + rr[2]*hwr.z + rr[3]*hwr.w
             + ii[0]*hwi.x + ii[1]*hwi.y + ii[2]*hwi.z + ii[3]*hwi.w;
    *(float4*)(pp + 4 * t) = make_float4(rr[0], rr[1], rr[2], rr[3]);
    *(float4*)(pp + Dc + 4 * t) = make_float4(ii[0], ii[1], ii[2], ii[3]);
    sA = blockSum128(sA); cA = blockSum128(cA); hA = blockSum128(hA);
    if (t == 0) {
        g_score[row] = sA + score_b[m];
        g_conf[row]  = sigm(cA + conf_b[m]);
        g_halt[row]  = sigm(hA + halt_b[m]);
    }
}

// fused stack pipeline; flat comes precomputed in g_flat (zeroed here after use)
__global__ void k_stack(const float* __restrict__ cw,  const float* __restrict__ cb,
                        const float* __restrict__ stw, const float* __restrict__ stb,
                        const float* __restrict__ scw, const float* __restrict__ scb) {
    __shared__ float s_red[8];
    __shared__ float s_ptr[Kc], s_wmask[Kc];
    const int b = blockIdx.x, t = threadIdx.x;   // 256 threads
    const int e0 = 4 * t;                        // covers 1024

    float4 fv = *(float4*)(g_flat + b * E2 + e0);
    *(float4*)(g_flat + b * E2 + e0) = make_float4(0.f, 0.f, 0.f, 0.f);  // reset for next accumulate

    // control logits (cw strided by 3)
    float a0 = fv.x * cw[e0 * 3]     + fv.y * cw[(e0 + 1) * 3]     + fv.z * cw[(e0 + 2) * 3]     + fv.w * cw[(e0 + 3) * 3];
    float a1 = fv.x * cw[e0 * 3 + 1] + fv.y * cw[(e0 + 1) * 3 + 1] + fv.z * cw[(e0 + 2) * 3 + 1] + fv.w * cw[(e0 + 3) * 3 + 1];
    float a2 = fv.x * cw[e0 * 3 + 2] + fv.y * cw[(e0 + 1) * 3 + 2] + fv.z * cw[(e0 + 2) * 3 + 2] + fv.w * cw[(e0 + 3) * 3 + 2];
    a0 = blockSum256(a0, s_red); a1 = blockSum256(a1, s_red); a2 = blockSum256(a2, s_red);
    a0 += cb[0]; a1 += cb[1]; a2 += cb[2];
    float mx3 = fmaxf(a0, fmaxf(a1, a2));
    float e0e = expf(a0 - mx3), e1e = expf(a1 - mx3), e2e = expf(a2 - mx3);
    float is3 = 1.f / (e0e + e1e + e2e);
    float push = e0e * is3, pop = e1e * is3, noop = e2e * is3;

    if (t < Kc) {
        float* P = g_ptrst + b * Kc;
        float pu = P[(t + Kc - 1) % Kc];
        float pd = P[(t + 1) % Kc];
        float pc = P[t];
        float np = push * pu + pop * pd + noop * pc;
        float s = np;
#pragma unroll
        for (int o = 16; o; o >>= 1) s += __shfl_xor_sync(0xffffffffu, s, o);
        np /= (s + EPSF);
        P[t] = np;
        s_ptr[t] = np;
        s_wmask[t] = push * pu;
    }
    __syncthreads();

    // mem update + read + st dots (float4 per thread)
    float4 racc = make_float4(0.f, 0.f, 0.f, 0.f);
#pragma unroll
    for (int k = 0; k < Kc; k++) {
        float w = s_wmask[k], pk = s_ptr[k];
        float4* mp = (float4*)(g_mem + ((size_t)(b * Kc + k)) * E2 + e0);
        float4 old = *mp;
        float4 nm = make_float4(fmaf(w, fv.x - old.x, old.x), fmaf(w, fv.y - old.y, old.y),
                                fmaf(w, fv.z - old.z, old.z), fmaf(w, fv.w - old.w, old.w));
        *mp = nm;
        racc.x += nm.x * pk; racc.y += nm.y * pk; racc.z += nm.z * pk; racc.w += nm.w * pk;
    }
    *(float4*)(g_read + b * E2 + e0) = racc;
    float4 w1 = *(const float4*)(stw + e0);
    float4 w2 = *(const float4*)(scw + e0);
    float s1 = racc.x * w1.x + racc.y * w1.y + racc.z * w1.z + racc.w * w1.w;
    float s2 = racc.x * w2.x + racc.y * w2.y + racc.z * w2.z + racc.w * w2.w;
    float h = 0.f;
    for (int idx = t; idx < Mc * Sc; idx += 256)
        h += g_halt[(idx >> 7) * NBS + b * Sc + (idx & 127)];
    s1 = blockSum256(s1, s_red); s2 = blockSum256(s2, s_red); h = blockSum256(h, s_red);
    if (t == 0) {
        g_stsc[b] = s1 + stb[0];
        g_stcf[b] = sigm(s2 + scb[0]);
        float p = h * (1.f / (Mc * Sc));
        float rm = g_rem[b];
        g_coef[b] = p * rm;
        g_rem[b] = rm * (1.f - p);
    }
}

// combine + state/acc + NEXT-step C + flat accumulation + logits zero
__global__ void k_combine(const float* __restrict__ xr, const float* __restrict__ xi) {
    const int bs = blockIdx.x;
    const int b = bs >> 7;
    float l[5];
#pragma unroll
    for (int m = 0; m < Mc; m++)
        l[m] = g_score[m * NBS + bs] * g_conf[m * NBS + bs];
    l[4] = g_stsc[b] * g_stcf[b];
    float mx = l[0];
#pragma unroll
    for (int m = 1; m < 5; m++) mx = fmaxf(mx, l[m]);
    float w[5], s = 0.f;
#pragma unroll
    for (int m = 0; m < 5; m++) { w[m] = expf(l[m] - mx); s += w[m]; }
    float is = 1.f / s;
#pragma unroll
    for (int m = 0; m < 5; m++) w[m] *= is;
    float cf = g_coef[b];
    const int t = threadIdx.x;
    const int d0 = 4 * t;   // 128 thr x 4 = 512 = Dc

    float4 rd = *(const float4*)(g_read + b * E2 + d0);
    float4 ri = *(const float4*)(g_read + b * E2 + Dc + d0);
    float nr[4] = {w[4] * rd.x, w[4] * rd.y, w[4] * rd.z, w[4] * rd.w};
    float ni[4] = {w[4] * ri.x, w[4] * ri.y, w[4] * ri.z, w[4] * ri.w};
#pragma unroll
    for (int m = 0; m < Mc; m++) {
        const float* pb = g_P + ((size_t)m * NBS + bs) * E2;
        float4 pr = *(const float4*)(pb + d0);
        float4 pi = *(const float4*)(pb + Dc + d0);
        nr[0] += w[m] * pr.x; nr[1] += w[m] * pr.y; nr[2] += w[m] * pr.z; nr[3] += w[m] * pr.w;
        ni[0] += w[m] * pi.x; ni[1] += w[m] * pi.y; ni[2] += w[m] * pi.z; ni[3] += w[m] * pi.w;
    }
    *(float4*)(g_sr + (size_t)bs * Dc + d0) = make_float4(nr[0], nr[1], nr[2], nr[3]);
    *(float4*)(g_si + (size_t)bs * Dc + d0) = make_float4(ni[0], ni[1], ni[2], ni[3]);
    float4 a0 = *(float4*)(g_acc + (size_t)bs * E2 + d0);
    float4 a1 = *(float4*)(g_acc + (size_t)bs * E2 + Dc + d0);
    a0.x += cf * nr[0]; a0.y += cf * nr[1]; a0.z += cf * nr[2]; a0.w += cf * nr[3];
    a1.x += cf * ni[0]; a1.y += cf * ni[1]; a1.z += cf * ni[2]; a1.w += cf * ni[3];
    *(float4*)(g_acc + (size_t)bs * E2 + d0) = a0;
    *(float4*)(g_acc + (size_t)bs * E2 + Dc + d0) = a1;

    // next-step C = 0.5*(x + s_new), split bf16 (packed stores)
    float4 x0 = *(const float4*)(xr + (size_t)bs * Dc + d0);
    float4 x1 = *(const float4*)(xi + (size_t)bs * Dc + d0);
    float cr[4] = {0.5f * (x0.x + nr[0]), 0.5f * (x0.y + nr[1]), 0.5f * (x0.z + nr[2]), 0.5f * (x0.w + nr[3])};
    float ci[4] = {0.5f * (x1.x + ni[0]), 0.5f * (x1.y + ni[1]), 0.5f * (x1.z + ni[2]), 0.5f * (x1.w + ni[3])};
    *(uint2*)(g_Ch + (size_t)bs * E2 + d0) = make_uint2(pkbf2(cr[0], cr[1]), pkbf2(cr[2], cr[3]));
    *(uint2*)(g_Cl + (size_t)bs * E2 + d0) = make_uint2(pkbf2(bflo(cr[0]), bflo(cr[1])), pkbf2(bflo(cr[2]), bflo(cr[3])));
    *(uint2*)(g_Ch + (size_t)bs * E2 + Dc + d0) = make_uint2(pkbf2(ci[0], ci[1]), pkbf2(ci[2], ci[3]));
    *(uint2*)(g_Cl + (size_t)bs * E2 + Dc + d0) = make_uint2(pkbf2(bflo(ci[0]), bflo(ci[1])), pkbf2(bflo(ci[2]), bflo(ci[3])));

    // accumulate next step's flat_in = mean over S of new state
    constexpr float invS = 1.f / Sc;
#pragma unroll
    for (int q = 0; q < 4; q++) {
        atomicAdd(g_flat + b * E2 + d0 + q, nr[q] * invS);
        atomicAdd(g_flat + b * E2 + Dc + d0 + q, ni[q] * invS);
    }
    // zero logits for next step's split-K atomics
    *(float4*)(g_logits + (size_t)bs * 512 + d0) = make_float4(0.f, 0.f, 0.f, 0.f);
}

__global__ void k_final(float* __restrict__ out) {
    int i = blockIdx.x * 256 + threadIdx.x;   // 524288
    int bs = i >> 10, e = i & 1023;
    int b = bs >> 7;
    float st = (e < Dc) ? g_sr[(size_t)bs * Dc + e]
                        : g_si[(size_t)bs * Dc + (e - Dc)];
    out[i] = g_acc[i] + g_rem[b] * st;
}

// ---------------------------------------------------------------------------
extern "C" void kernel_launch(void* const* d_in, const int* in_sizes, int n_in,
                              void* d_out, int out_size) {
    const float* xr        = (const float*)d_in[0];
    const float* xi        = (const float*)d_in[1];
    const float* Wl_r      = (const float*)d_in[2];
    const float* Wl_i      = (const float*)d_in[3];
    const float* Wq_r      = (const float*)d_in[4];
    const float* Wq_i      = (const float*)d_in[5];
    const float* Wk_r      = (const float*)d_in[6];
    const float* Wk_i      = (const float*)d_in[7];
    const float* Wv_r      = (const float*)d_in[8];
    const float* Wv_i      = (const float*)d_in[9];
    const float* ln_scale  = (const float*)d_in[10];
    const float* ln_shift  = (const float*)d_in[11];
    const float* mod_bias  = (const float*)d_in[12];
    const float* gate_mask = (const float*)d_in[13];
    const float* score_w   = (const float*)d_in[14];
    const float* score_b   = (const float*)d_in[15];
    const float* conf_w    = (const float*)d_in[16];
    const float* conf_b    = (const float*)d_in[17];
    const float* halt_w    = (const float*)d_in[18];
    const float* halt_b    = (const float*)d_in[19];
    const float* ctrl_w    = (const float*)d_in[20];
    const float* ctrl_b    = (const float*)d_in[21];
    const float* st_score_w= (const float*)d_in[22];
    const float* st_score_b= (const float*)d_in[23];
    const float* st_conf_w = (const float*)d_in[24];
    const float* st_conf_b = (const float*)d_in[25];

    cudaFuncSetAttribute(gemm_mma<0,false>, cudaFuncAttributeMaxDynamicSharedMemorySize, GEMM_SMEM);
    cudaFuncSetAttribute(gemm_mma<3,true>,  cudaFuncAttributeMaxDynamicSharedMemorySize, GEMM_SMEM);
    cudaFuncSetAttribute(gemm_qkv,          cudaFuncAttributeMaxDynamicSharedMemorySize, GEMM_SMEM);

    __nv_bfloat16 *WPH, *WPL, *Ch, *Cl, *Zh, *Zl, *Qh, *Ql, *Kh, *Kl, *Vth, *Vtl, *ATh, *ATl;
    float *Z, *LG, *P;
    cudaGetSymbolAddress((void**)&WPH, g_WPH);
    cudaGetSymbolAddress((void**)&WPL, g_WPL);
    cudaGetSymbolAddress((void**)&Ch, g_Ch);
    cudaGetSymbolAddress((void**)&Cl, g_Cl);
    cudaGetSymbolAddress((void**)&Z, g_Z);
    cudaGetSymbolAddress((void**)&Zh, g_Zh);
    cudaGetSymbolAddress((void**)&Zl, g_Zl);
    cudaGetSymbolAddress((void**)&Qh, g_Qh);
    cudaGetSymbolAddress((void**)&Ql, g_Ql);
    cudaGetSymbolAddress((void**)&Kh, g_Kh);
    cudaGetSymbolAddress((void**)&Kl, g_Kl);
    cudaGetSymbolAddress((void**)&Vth, g_Vth);
    cudaGetSymbolAddress((void**)&Vtl, g_Vtl);
    cudaGetSymbolAddress((void**)&LG, g_logits);
    cudaGetSymbolAddress((void**)&ATh, g_ATh);
    cudaGetSymbolAddress((void**)&ATl, g_ATl);
    cudaGetSymbolAddress((void**)&P, g_P);

    k_pack<<<65536, 256>>>(Wl_r, Wl_i, Wq_r, Wq_i, Wk_r, Wk_i, Wv_r, Wv_i);
    k_init<<<2048, 256>>>(xr, xi, gate_mask);

    for (int step = 0; step < NSTEPS; step++) {
        // Z = C x WlP  (A shared over modules)
        gemm_mma<0,false><<<dim3(8, 4, Mc), 256, GEMM_SMEM>>>(
            Ch, Cl, E2, 0,
            WPH + 0 * WTYPE, WPL + 0 * WTYPE, E2, WMOD,
            Z, E2, (size_t)ROWS * E2, E2);
        k_norm<<<NMBS, 128>>>(ln_scale, ln_shift, mod_bias);
        // fused Q,K,V projections
        gemm_qkv<<<dim3(24, 4, Mc), 256, GEMM_SMEM>>>(
            Zh, Zl, WPH + 1 * WTYPE, WPL + 1 * WTYPE,
            Qh, Ql, Kh, Kl, Vth, Vtl);
        // logits = Q.K^T (split-K=4, atomic accumulate into zeroed buffer)
        gemm_mma<3,true><<<dim3(1, 4, 16), 256, GEMM_SMEM>>>(
            Qh, Ql, E2, (size_t)Sc * E2,
            Kh, Kl, E2, (size_t)Sc * E2,
            LG, Sc, (size_t)Sc * Sc, 256);
        k_softmax<<<16 * Sc, 128>>>();
        // P = attn . Vt^T   (K = 128)
        gemm_mma<0,false><<<dim3(8, 1, 16), 256, GEMM_SMEM>>>(
            ATh, ATl, Sc, (size_t)Sc * Sc,
            Vth, Vtl, Sc, (size_t)E2 * Sc,
            P, E2, (size_t)Sc * E2, Sc);
        k_gatescore<<<NMBS, 128>>>(score_w, score_b, conf_w, conf_b, halt_w, halt_b);
        k_stack<<<Bc, 256>>>(ctrl_w, ctrl_b, st_score_w, st_score_b, st_conf_w, st_conf_b);
        k_combine<<<NBS, 128>>>(xr, xi);
    }
    k_final<<<2048, 256>>>((float*)d_out);
}